// round 1
// baseline (speedup 1.0000x reference)
#include <cuda_runtime.h>
#include <math.h>

#define B_   8
#define N1_  4096
#define N2_  256
#define D_   1024
#define INNER_ 1024
#define HEADS_ 16
#define DH_  64
#define L_   (N1_ + N2_)   // 4352
#define EPS_ 1e-5f

// ---------------- scratch (device globals; no runtime allocation) ----------------
__device__ float g_kvin[(size_t)B_ * L_ * D_];          // normalized [xn ; latm] per batch  (142.6 MB)
__device__ float g_latm[(size_t)B_ * N2_ * D_];          // modulated latents, contiguous     (8 MB)
__device__ float g_q   [(size_t)B_ * N2_ * INNER_];      // q projection                      (8 MB)
__device__ float g_kv  [(size_t)B_ * L_ * 2 * INNER_];   // [k | v] projection                (285 MB)
__device__ float g_att [(size_t)B_ * N2_ * INNER_];      // attention output                  (8 MB)

// ---------------- LayerNorm (+ modulation for latent rows) ----------------
// One block per row (B*L rows). Row-major D=1024, 256 threads x 4 floats.
__global__ __launch_bounds__(256)
void ln_kernel(const float* __restrict__ x, const float* __restrict__ latents,
               const float* __restrict__ shift, const float* __restrict__ scale,
               const float* __restrict__ ln1w, const float* __restrict__ ln1b,
               const float* __restrict__ ln2w, const float* __restrict__ ln2b)
{
    const int row   = blockIdx.x;           // 0 .. B*L-1
    const int batch = row / L_;
    const int local = row % L_;
    const bool is_lat = (local >= N1_);

    const float* src = is_lat
        ? latents + ((size_t)batch * N2_ + (local - N1_)) * D_
        : x       + ((size_t)batch * N1_ + local) * D_;

    const int t = threadIdx.x;
    float4 v = reinterpret_cast<const float4*>(src)[t];   // 4 floats per thread

    float s  = v.x + v.y + v.z + v.w;
    float sq = v.x*v.x + v.y*v.y + v.z*v.z + v.w*v.w;

    // block reduce (sum, sumsq)
    __shared__ float red[16];
    __shared__ float red2[16];
    for (int o = 16; o > 0; o >>= 1) {
        s  += __shfl_down_sync(0xffffffff, s,  o);
        sq += __shfl_down_sync(0xffffffff, sq, o);
    }
    int warp = t >> 5, lane = t & 31;
    if (lane == 0) { red[warp] = s; red2[warp] = sq; }
    __syncthreads();
    if (warp == 0) {
        s  = (lane < 8) ? red[lane]  : 0.f;
        sq = (lane < 8) ? red2[lane] : 0.f;
        for (int o = 4; o > 0; o >>= 1) {
            s  += __shfl_down_sync(0xffffffff, s,  o);
            sq += __shfl_down_sync(0xffffffff, sq, o);
        }
        if (lane == 0) { red[0] = s; red2[0] = sq; }
    }
    __syncthreads();
    const float mu   = red[0] * (1.0f / D_);
    const float var  = red2[0] * (1.0f / D_) - mu * mu;
    const float rstd = rsqrtf(var + EPS_);

    const int k0 = t * 4;
    float4 w4, b4, out;
    if (is_lat) {
        w4 = reinterpret_cast<const float4*>(ln2w)[t];
        b4 = reinterpret_cast<const float4*>(ln2b)[t];
    } else {
        w4 = reinterpret_cast<const float4*>(ln1w)[t];
        b4 = reinterpret_cast<const float4*>(ln1b)[t];
    }
    out.x = (v.x - mu) * rstd * w4.x + b4.x;
    out.y = (v.y - mu) * rstd * w4.y + b4.y;
    out.z = (v.z - mu) * rstd * w4.z + b4.z;
    out.w = (v.w - mu) * rstd * w4.w + b4.w;

    if (is_lat) {
        const float4 sc = reinterpret_cast<const float4*>(scale + (size_t)batch * D_)[t];
        const float4 sh = reinterpret_cast<const float4*>(shift + (size_t)batch * D_)[t];
        out.x = out.x * (1.0f + sc.x) + sh.x;
        out.y = out.y * (1.0f + sc.y) + sh.y;
        out.z = out.z * (1.0f + sc.z) + sh.z;
        out.w = out.w * (1.0f + sc.w) + sh.w;
        reinterpret_cast<float4*>(g_latm + ((size_t)batch * N2_ + (local - N1_)) * D_)[t] = out;
    }
    reinterpret_cast<float4*>(g_kvin + (size_t)row * D_)[t] = out;
    (void)k0;
}

// ---------------- NT GEMM: C[M,N] = A[M,K] * W[N,K]^T (both K-contiguous) ----------------
// 128x128 tile, BK=16, 256 threads, 8x8 per thread. M,N multiples of 128; K multiple of 16.
#define BM 128
#define BN 128
#define BK 16
__global__ __launch_bounds__(256)
void gemm_nt(const float* __restrict__ A, const float* __restrict__ W,
             float* __restrict__ C, int M, int N, int K)
{
    __shared__ float As[BK][BM];
    __shared__ float Bs[BK][BN];

    const int bm = blockIdx.y * BM;
    const int bn = blockIdx.x * BN;
    const int tid = threadIdx.x;
    const int tx = tid & 15;      // 0..15
    const int ty = tid >> 4;      // 0..15

    const int lrow = tid >> 2;        // 0..63
    const int lcol = (tid & 3) * 4;   // 0,4,8,12

    float acc[8][8];
    #pragma unroll
    for (int i = 0; i < 8; i++)
        #pragma unroll
        for (int j = 0; j < 8; j++) acc[i][j] = 0.f;

    for (int k0 = 0; k0 < K; k0 += BK) {
        #pragma unroll
        for (int h = 0; h < 2; h++) {
            int r = lrow + h * 64;
            float4 va = *reinterpret_cast<const float4*>(&A[(size_t)(bm + r) * K + k0 + lcol]);
            As[lcol+0][r] = va.x; As[lcol+1][r] = va.y; As[lcol+2][r] = va.z; As[lcol+3][r] = va.w;
            float4 vb = *reinterpret_cast<const float4*>(&W[(size_t)(bn + r) * K + k0 + lcol]);
            Bs[lcol+0][r] = vb.x; Bs[lcol+1][r] = vb.y; Bs[lcol+2][r] = vb.z; Bs[lcol+3][r] = vb.w;
        }
        __syncthreads();

        #pragma unroll
        for (int k = 0; k < BK; k++) {
            float a[8], b[8];
            #pragma unroll
            for (int i = 0; i < 4; i++) {
                float4 t4 = *reinterpret_cast<const float4*>(&As[k][ty * 8 + i * 4]);
                a[i*4+0]=t4.x; a[i*4+1]=t4.y; a[i*4+2]=t4.z; a[i*4+3]=t4.w;
                i++;
                t4 = *reinterpret_cast<const float4*>(&As[k][ty * 8 + (i) * 4 - 4 + 4]);
                (void)t4; i--; // (kept simple below)
            }
            // simpler explicit vector loads:
            {
                float4 a0 = *reinterpret_cast<const float4*>(&As[k][ty * 8 + 0]);
                float4 a1 = *reinterpret_cast<const float4*>(&As[k][ty * 8 + 4]);
                a[0]=a0.x; a[1]=a0.y; a[2]=a0.z; a[3]=a0.w;
                a[4]=a1.x; a[5]=a1.y; a[6]=a1.z; a[7]=a1.w;
                float4 b0 = *reinterpret_cast<const float4*>(&Bs[k][tx * 8 + 0]);
                float4 b1 = *reinterpret_cast<const float4*>(&Bs[k][tx * 8 + 4]);
                b[0]=b0.x; b[1]=b0.y; b[2]=b0.z; b[3]=b0.w;
                b[4]=b1.x; b[5]=b1.y; b[6]=b1.z; b[7]=b1.w;
            }
            #pragma unroll
            for (int i = 0; i < 8; i++)
                #pragma unroll
                for (int j = 0; j < 8; j++)
                    acc[i][j] = fmaf(a[i], b[j], acc[i][j]);
        }
        __syncthreads();
    }

    #pragma unroll
    for (int i = 0; i < 8; i++) {
        float4* dst0 = reinterpret_cast<float4*>(&C[(size_t)(bm + ty * 8 + i) * N + bn + tx * 8]);
        float4 o0 = make_float4(acc[i][0], acc[i][1], acc[i][2], acc[i][3]);
        float4 o1 = make_float4(acc[i][4], acc[i][5], acc[i][6], acc[i][7]);
        dst0[0] = o0; dst0[1] = o1;
    }
}

// ---------------- Flash attention (fp32, online softmax) ----------------
// grid.x = B*HEADS (128), grid.y = 2 (q tiles of 128). 128 threads, 1 query per thread.
#define TK 64
__global__ __launch_bounds__(128)
void attn_kernel()
{
    __shared__ float Ks[TK][DH_];
    __shared__ float Vs[TK][DH_];
    __shared__ float Sm[TK][128];     // S[j][thread]

    const int bh    = blockIdx.x;
    const int batch = bh / HEADS_;
    const int head  = bh % HEADS_;
    const int tid   = threadIdx.x;
    const int qi    = blockIdx.y * 128 + tid;   // query index within N2

    // load q, fold attn scale (1/sqrt(sqrt(dh)))^2 = 1/8
    float q[DH_];
    {
        const float* qp = g_q + ((size_t)batch * N2_ + qi) * INNER_ + head * DH_;
        #pragma unroll
        for (int d = 0; d < DH_; d += 4) {
            float4 v = *reinterpret_cast<const float4*>(qp + d);
            q[d+0] = v.x * 0.125f; q[d+1] = v.y * 0.125f;
            q[d+2] = v.z * 0.125f; q[d+3] = v.w * 0.125f;
        }
    }

    float m = -INFINITY, l = 0.f;
    float acc[DH_];
    #pragma unroll
    for (int d = 0; d < DH_; d++) acc[d] = 0.f;

    const int lrow  = tid >> 1;            // 0..63
    const int lpart = (tid & 1) * 32;      // 0 or 32
    const size_t kvrow_base = (size_t)batch * L_;

    for (int t = 0; t < L_ / TK; t++) {
        // cooperative load of K,V tiles (2 threads per row, 32 floats each)
        {
            const int key = t * TK + lrow;
            const float* kp = g_kv + (kvrow_base + key) * (2 * INNER_) + head * DH_ + lpart;
            const float* vp = kp + INNER_;
            #pragma unroll
            for (int i = 0; i < 8; i++) {
                float4 kv4 = *reinterpret_cast<const float4*>(kp + i * 4);
                *reinterpret_cast<float4*>(&Ks[lrow][lpart + i * 4]) = kv4;
                float4 vv4 = *reinterpret_cast<const float4*>(vp + i * 4);
                *reinterpret_cast<float4*>(&Vs[lrow][lpart + i * 4]) = vv4;
            }
        }
        __syncthreads();

        // logits for this tile
        float tm = -INFINITY;
        #pragma unroll 2
        for (int j = 0; j < TK; j++) {
            float s = 0.f;
            #pragma unroll
            for (int d = 0; d < DH_; d++) s = fmaf(q[d], Ks[j][d], s);
            Sm[j][tid] = s;
            tm = fmaxf(tm, s);
        }

        const float m_new = fmaxf(m, tm);
        const float corr  = __expf(m - m_new);
        l *= corr;
        #pragma unroll
        for (int d = 0; d < DH_; d++) acc[d] *= corr;

        #pragma unroll 2
        for (int j = 0; j < TK; j++) {
            float p = __expf(Sm[j][tid] - m_new);
            l += p;
            #pragma unroll
            for (int d = 0; d < DH_; d++) acc[d] = fmaf(p, Vs[j][d], acc[d]);
        }
        m = m_new;
        __syncthreads();
    }

    const float inv_l = 1.0f / l;
    float* op = g_att + ((size_t)batch * N2_ + qi) * INNER_ + head * DH_;
    #pragma unroll
    for (int d = 0; d < DH_; d += 4) {
        float4 o = make_float4(acc[d] * inv_l, acc[d+1] * inv_l, acc[d+2] * inv_l, acc[d+3] * inv_l);
        *reinterpret_cast<float4*>(op + d) = o;
    }
}

// ---------------- launch ----------------
extern "C" void kernel_launch(void* const* d_in, const int* in_sizes, int n_in,
                              void* d_out, int out_size)
{
    const float* x       = (const float*)d_in[0];
    const float* latents = (const float*)d_in[1];
    const float* shift   = (const float*)d_in[2];
    const float* scale   = (const float*)d_in[3];
    const float* ln1w    = (const float*)d_in[4];
    const float* ln1b    = (const float*)d_in[5];
    const float* ln2w    = (const float*)d_in[6];
    const float* ln2b    = (const float*)d_in[7];
    const float* Wq      = (const float*)d_in[8];
    const float* Wkv     = (const float*)d_in[9];
    const float* Wo      = (const float*)d_in[10];
    float* out = (float*)d_out;

    float* kvin = nullptr; float* latm = nullptr; float* qb = nullptr;
    float* kvb = nullptr;  float* attb = nullptr;
    cudaGetSymbolAddress((void**)&kvin, g_kvin);
    cudaGetSymbolAddress((void**)&latm, g_latm);
    cudaGetSymbolAddress((void**)&qb,   g_q);
    cudaGetSymbolAddress((void**)&kvb,  g_kv);
    cudaGetSymbolAddress((void**)&attb, g_att);

    // 1) LayerNorms + modulation
    ln_kernel<<<B_ * L_, 256>>>(x, latents, shift, scale, ln1w, ln1b, ln2w, ln2b);

    // 2) q = latm @ Wq^T : M=2048, N=1024
    {
        dim3 grid(INNER_ / BN, (B_ * N2_) / BM);
        gemm_nt<<<grid, 256>>>(latm, Wq, qb, B_ * N2_, INNER_, D_);
    }
    // 3) kv = kvin @ Wkv^T : M=34816, N=2048
    {
        dim3 grid((2 * INNER_) / BN, (B_ * L_) / BM);
        gemm_nt<<<grid, 256>>>(kvin, Wkv, kvb, B_ * L_, 2 * INNER_, D_);
    }
    // 4) attention
    {
        dim3 grid(B_ * HEADS_, N2_ / 128);
        attn_kernel<<<grid, 128>>>();
    }
    // 5) out = att @ Wo^T : M=2048, N=1024
    {
        dim3 grid(D_ / BN, (B_ * N2_) / BM);
        gemm_nt<<<grid, 256>>>(attb, Wo, out, B_ * N2_, D_, INNER_);
    }
    (void)in_sizes; (void)n_in; (void)out_size;
}

// round 3
// speedup vs baseline: 1.5439x; 1.5439x over previous
#include <cuda_runtime.h>
#include <cuda_bf16.h>
#include <math.h>
#include <stdint.h>

#define B_   8
#define N1_  4096
#define N2_  256
#define D_   1024
#define INNER_ 1024
#define HEADS_ 16
#define DH_  64
#define L_   (N1_ + N2_)   // 4352
#define EPS_ 1e-5f

// ---------------- scratch (device globals; no runtime allocation) ----------------
__device__ __nv_bfloat16 g_kvin_hi[(size_t)B_ * L_ * D_];
__device__ __nv_bfloat16 g_kvin_lo[(size_t)B_ * L_ * D_];
__device__ __nv_bfloat16 g_latm_hi[(size_t)B_ * N2_ * D_];
__device__ __nv_bfloat16 g_latm_lo[(size_t)B_ * N2_ * D_];
__device__ __nv_bfloat16 g_wq_hi[(size_t)INNER_ * D_];
__device__ __nv_bfloat16 g_wq_lo[(size_t)INNER_ * D_];
__device__ __nv_bfloat16 g_wkv_hi[(size_t)2 * INNER_ * D_];
__device__ __nv_bfloat16 g_wkv_lo[(size_t)2 * INNER_ * D_];
__device__ __nv_bfloat16 g_wo_hi[(size_t)D_ * INNER_];
__device__ __nv_bfloat16 g_wo_lo[(size_t)D_ * INNER_];
__device__ __nv_bfloat16 g_att_hi[(size_t)B_ * N2_ * INNER_];
__device__ __nv_bfloat16 g_att_lo[(size_t)B_ * N2_ * INNER_];
__device__ float g_q [(size_t)B_ * N2_ * INNER_];
__device__ float g_kv[(size_t)B_ * L_ * 2 * INNER_];

// ============================ PTX helpers ============================
__device__ __forceinline__ uint32_t smem_u32(const void* p) {
    uint32_t a;
    asm("{ .reg .u64 t; cvta.to.shared.u64 t, %1; cvt.u32.u64 %0, t; }"
        : "=r"(a) : "l"(p));
    return a;
}

#define CP_ASYNC16(dst, src) \
    asm volatile("cp.async.cg.shared.global [%0], [%1], 16;" :: "r"(dst), "l"(src))
#define CP_COMMIT() asm volatile("cp.async.commit_group;" ::: "memory")
#define CP_WAIT(n)  asm volatile("cp.async.wait_group %0;" :: "n"(n) : "memory")

#define LDSM_X4(r, addr) \
    asm volatile("ldmatrix.sync.aligned.m8n8.x4.shared.b16 {%0,%1,%2,%3}, [%4];" \
                 : "=r"((r)[0]), "=r"((r)[1]), "=r"((r)[2]), "=r"((r)[3]) : "r"(addr))

#define MMA16816(acc, a, b0, b1) \
    asm volatile("mma.sync.aligned.m16n8k16.row.col.f32.bf16.bf16.f32 " \
        "{%0,%1,%2,%3}, {%4,%5,%6,%7}, {%8,%9}, {%0,%1,%2,%3};" \
        : "+f"((acc)[0]), "+f"((acc)[1]), "+f"((acc)[2]), "+f"((acc)[3]) \
        : "r"((a)[0]), "r"((a)[1]), "r"((a)[2]), "r"((a)[3]), "r"(b0), "r"(b1))

__device__ __forceinline__ void split_hl(float v, __nv_bfloat16& h, __nv_bfloat16& l) {
    h = __float2bfloat16_rn(v);
    l = __float2bfloat16_rn(v - __bfloat162float(h));
}

// ============================ bf16x3 mma.sync GEMM ============================
// C[M,N] = A[M,K] * W[N,K]^T with A,W given as bf16 (hi,lo) pairs; fp32 accumulate.
// Tile 128x128, BK=32, 2-stage cp.async pipeline, 256 threads (8 warps, 4x2).
// smem per stage: 4 arrays x 128 rows x 40 bf16 (pad) = 40960 B; 2 stages = 81920 B.
#define GS_STAGE 40960
#define GS_ARR   10240
#define GS_ROWB  80

__global__ __launch_bounds__(256, 1)
void gemm_bf16x3(const __nv_bfloat16* __restrict__ Ah, const __nv_bfloat16* __restrict__ Al,
                 const __nv_bfloat16* __restrict__ Bh, const __nv_bfloat16* __restrict__ Bl,
                 float* __restrict__ C, int M, int N, int K)
{
    extern __shared__ char smraw[];
    const uint32_t smbase = smem_u32(smraw);

    const int tid  = threadIdx.x;
    const int wid  = tid >> 5;
    const int lane = tid & 31;
    const int bm = blockIdx.y * 128;
    const int bn = blockIdx.x * 128;
    const int wm = (wid & 3) * 32;   // warp m-offset (4 warps down)
    const int wn = (wid >> 2) * 64;  // warp n-offset (2 warps across)

    const char* srcs[4] = { (const char*)Ah, (const char*)Al,
                            (const char*)Bh, (const char*)Bl };

    auto load_stage = [&](int kt, int st) {
        #pragma unroll
        for (int arr = 0; arr < 4; arr++) {
            const int rb = (arr < 2) ? bm : bn;
            #pragma unroll
            for (int j = 0; j < 2; j++) {
                const int ch  = tid * 2 + j;      // 0..511
                const int row = ch >> 2;
                const int col = ch & 3;
                const char* src = srcs[arr]
                    + ((size_t)(rb + row) * K + kt * 32) * 2 + col * 16;
                const uint32_t dst = smbase + st * GS_STAGE + arr * GS_ARR
                    + row * GS_ROWB + col * 16;
                CP_ASYNC16(dst, src);
            }
        }
    };

    float acc[2][8][4];
    #pragma unroll
    for (int i = 0; i < 2; i++)
        #pragma unroll
        for (int t = 0; t < 8; t++)
            #pragma unroll
            for (int c = 0; c < 4; c++) acc[i][t][c] = 0.f;

    const int niter = K / 32;
    load_stage(0, 0);
    CP_COMMIT();

    for (int kt = 0; kt < niter; kt++) {
        const int st = kt & 1;
        if (kt + 1 < niter) {
            load_stage(kt + 1, st ^ 1);
            CP_COMMIT();
            CP_WAIT(1);
        } else {
            CP_WAIT(0);
        }
        __syncthreads();

        const uint32_t base = smbase + st * GS_STAGE;
        #pragma unroll
        for (int kk = 0; kk < 2; kk++) {
            uint32_t ah[2][4], al[2][4], bh[4][4], bl[4][4];
            #pragma unroll
            for (int i = 0; i < 2; i++) {
                const uint32_t ra = base
                    + (uint32_t)((wm + i * 16 + (lane & 15)) * GS_ROWB
                                 + ((lane >> 4) << 4) + kk * 32);
                LDSM_X4(ah[i], ra);
                LDSM_X4(al[i], ra + GS_ARR);
            }
            #pragma unroll
            for (int g = 0; g < 4; g++) {
                const uint32_t rbb = base + 2 * GS_ARR
                    + (uint32_t)((wn + g * 16 + ((lane >> 4) << 3) + (lane & 7)) * GS_ROWB
                                 + (((lane >> 3) & 1) << 4) + kk * 32);
                LDSM_X4(bh[g], rbb);
                LDSM_X4(bl[g], rbb + GS_ARR);
            }
            #pragma unroll
            for (int i = 0; i < 2; i++) {
                #pragma unroll
                for (int g = 0; g < 4; g++) {
                    MMA16816(acc[i][2*g],   ah[i], bh[g][0], bh[g][1]);
                    MMA16816(acc[i][2*g],   ah[i], bl[g][0], bl[g][1]);
                    MMA16816(acc[i][2*g],   al[i], bh[g][0], bh[g][1]);
                    MMA16816(acc[i][2*g+1], ah[i], bh[g][2], bh[g][3]);
                    MMA16816(acc[i][2*g+1], ah[i], bl[g][2], bl[g][3]);
                    MMA16816(acc[i][2*g+1], al[i], bh[g][2], bh[g][3]);
                }
            }
        }
        __syncthreads();
    }

    // epilogue: c-frag rows (lane>>2, +8), cols 2*(lane&3)
    #pragma unroll
    for (int i = 0; i < 2; i++) {
        #pragma unroll
        for (int t = 0; t < 8; t++) {
            const int r0 = bm + wm + i * 16 + (lane >> 2);
            const int c  = bn + wn + t * 8 + (lane & 3) * 2;
            *reinterpret_cast<float2*>(&C[(size_t)r0 * N + c]) =
                make_float2(acc[i][t][0], acc[i][t][1]);
            *reinterpret_cast<float2*>(&C[(size_t)(r0 + 8) * N + c]) =
                make_float2(acc[i][t][2], acc[i][t][3]);
        }
    }
    (void)M;
}

// ---------------- weight split: fp32 -> bf16 hi/lo ----------------
__global__ __launch_bounds__(256)
void split_kernel(const float* __restrict__ src,
                  __nv_bfloat16* __restrict__ hi, __nv_bfloat16* __restrict__ lo, int n4)
{
    int i = blockIdx.x * blockDim.x + threadIdx.x;
    if (i >= n4) return;
    float4 v = reinterpret_cast<const float4*>(src)[i];
    __nv_bfloat16 h0,l0,h1,l1,h2,l2,h3,l3;
    split_hl(v.x, h0, l0); split_hl(v.y, h1, l1);
    split_hl(v.z, h2, l2); split_hl(v.w, h3, l3);
    __nv_bfloat162* hp = reinterpret_cast<__nv_bfloat162*>(hi);
    __nv_bfloat162* lp = reinterpret_cast<__nv_bfloat162*>(lo);
    hp[i*2]   = __nv_bfloat162(h0, h1);
    hp[i*2+1] = __nv_bfloat162(h2, h3);
    lp[i*2]   = __nv_bfloat162(l0, l1);
    lp[i*2+1] = __nv_bfloat162(l2, l3);
}

// ---------------- LayerNorm (+ modulation), writes bf16 hi/lo ----------------
__global__ __launch_bounds__(256)
void ln_kernel(const float* __restrict__ x, const float* __restrict__ latents,
               const float* __restrict__ shift, const float* __restrict__ scale,
               const float* __restrict__ ln1w, const float* __restrict__ ln1b,
               const float* __restrict__ ln2w, const float* __restrict__ ln2b)
{
    const int row   = blockIdx.x;
    const int batch = row / L_;
    const int local = row % L_;
    const bool is_lat = (local >= N1_);

    const float* src = is_lat
        ? latents + ((size_t)batch * N2_ + (local - N1_)) * D_
        : x       + ((size_t)batch * N1_ + local) * D_;

    const int t = threadIdx.x;
    float4 v = reinterpret_cast<const float4*>(src)[t];

    float s  = v.x + v.y + v.z + v.w;
    float sq = v.x*v.x + v.y*v.y + v.z*v.z + v.w*v.w;

    __shared__ float red[16];
    __shared__ float red2[16];
    for (int o = 16; o > 0; o >>= 1) {
        s  += __shfl_down_sync(0xffffffff, s,  o);
        sq += __shfl_down_sync(0xffffffff, sq, o);
    }
    int warp = t >> 5, lane = t & 31;
    if (lane == 0) { red[warp] = s; red2[warp] = sq; }
    __syncthreads();
    if (warp == 0) {
        s  = (lane < 8) ? red[lane]  : 0.f;
        sq = (lane < 8) ? red2[lane] : 0.f;
        for (int o = 4; o > 0; o >>= 1) {
            s  += __shfl_down_sync(0xffffffff, s,  o);
            sq += __shfl_down_sync(0xffffffff, sq, o);
        }
        if (lane == 0) { red[0] = s; red2[0] = sq; }
    }
    __syncthreads();
    const float mu   = red[0] * (1.0f / D_);
    const float var  = red2[0] * (1.0f / D_) - mu * mu;
    const float rstd = rsqrtf(var + EPS_);

    float4 w4, b4, out;
    if (is_lat) {
        w4 = reinterpret_cast<const float4*>(ln2w)[t];
        b4 = reinterpret_cast<const float4*>(ln2b)[t];
    } else {
        w4 = reinterpret_cast<const float4*>(ln1w)[t];
        b4 = reinterpret_cast<const float4*>(ln1b)[t];
    }
    out.x = (v.x - mu) * rstd * w4.x + b4.x;
    out.y = (v.y - mu) * rstd * w4.y + b4.y;
    out.z = (v.z - mu) * rstd * w4.z + b4.z;
    out.w = (v.w - mu) * rstd * w4.w + b4.w;

    if (is_lat) {
        const float4 sc = reinterpret_cast<const float4*>(scale + (size_t)batch * D_)[t];
        const float4 sh = reinterpret_cast<const float4*>(shift + (size_t)batch * D_)[t];
        out.x = out.x * (1.0f + sc.x) + sh.x;
        out.y = out.y * (1.0f + sc.y) + sh.y;
        out.z = out.z * (1.0f + sc.z) + sh.z;
        out.w = out.w * (1.0f + sc.w) + sh.w;
    }

    __nv_bfloat16 h0,l0,h1,l1,h2,l2,h3,l3;
    split_hl(out.x, h0, l0); split_hl(out.y, h1, l1);
    split_hl(out.z, h2, l2); split_hl(out.w, h3, l3);
    __nv_bfloat162 hA(h0, h1), hB(h2, h3), lA(l0, l1), lB(l2, l3);

    {
        __nv_bfloat162* hp = reinterpret_cast<__nv_bfloat162*>(g_kvin_hi + (size_t)row * D_);
        __nv_bfloat162* lp = reinterpret_cast<__nv_bfloat162*>(g_kvin_lo + (size_t)row * D_);
        hp[t*2] = hA; hp[t*2+1] = hB;
        lp[t*2] = lA; lp[t*2+1] = lB;
    }
    if (is_lat) {
        const size_t lrow = (size_t)batch * N2_ + (local - N1_);
        __nv_bfloat162* hp = reinterpret_cast<__nv_bfloat162*>(g_latm_hi + lrow * D_);
        __nv_bfloat162* lp = reinterpret_cast<__nv_bfloat162*>(g_latm_lo + lrow * D_);
        hp[t*2] = hA; hp[t*2+1] = hB;
        lp[t*2] = lA; lp[t*2+1] = lB;
    }
}

// ---------------- Flash attention (fp32, online softmax) ----------------
#define TK 64
__global__ __launch_bounds__(128)
void attn_kernel()
{
    __shared__ float Ks[TK][DH_];
    __shared__ float Vs[TK][DH_];
    __shared__ float Sm[TK][128];

    const int bh    = blockIdx.x;
    const int batch = bh / HEADS_;
    const int head  = bh % HEADS_;
    const int tid   = threadIdx.x;
    const int qi    = blockIdx.y * 128 + tid;

    float q[DH_];
    {
        const float* qp = g_q + ((size_t)batch * N2_ + qi) * INNER_ + head * DH_;
        #pragma unroll
        for (int d = 0; d < DH_; d += 4) {
            float4 v = *reinterpret_cast<const float4*>(qp + d);
            q[d+0] = v.x * 0.125f; q[d+1] = v.y * 0.125f;
            q[d+2] = v.z * 0.125f; q[d+3] = v.w * 0.125f;
        }
    }

    float m = -INFINITY, l = 0.f;
    float acc[DH_];
    #pragma unroll
    for (int d = 0; d < DH_; d++) acc[d] = 0.f;

    const int lrow  = tid >> 1;
    const int lpart = (tid & 1) * 32;
    const size_t kvrow_base = (size_t)batch * L_;

    for (int t = 0; t < L_ / TK; t++) {
        {
            const int key = t * TK + lrow;
            const float* kp = g_kv + (kvrow_base + key) * (2 * INNER_) + head * DH_ + lpart;
            const float* vp = kp + INNER_;
            #pragma unroll
            for (int i = 0; i < 8; i++) {
                float4 kv4 = *reinterpret_cast<const float4*>(kp + i * 4);
                *reinterpret_cast<float4*>(&Ks[lrow][lpart + i * 4]) = kv4;
                float4 vv4 = *reinterpret_cast<const float4*>(vp + i * 4);
                *reinterpret_cast<float4*>(&Vs[lrow][lpart + i * 4]) = vv4;
            }
        }
        __syncthreads();

        float tm = -INFINITY;
        #pragma unroll 2
        for (int j = 0; j < TK; j++) {
            float s = 0.f;
            #pragma unroll
            for (int d = 0; d < DH_; d++) s = fmaf(q[d], Ks[j][d], s);
            Sm[j][tid] = s;
            tm = fmaxf(tm, s);
        }

        const float m_new = fmaxf(m, tm);
        const float corr  = __expf(m - m_new);
        l *= corr;
        #pragma unroll
        for (int d = 0; d < DH_; d++) acc[d] *= corr;

        #pragma unroll 2
        for (int j = 0; j < TK; j++) {
            float p = __expf(Sm[j][tid] - m_new);
            l += p;
            #pragma unroll
            for (int d = 0; d < DH_; d++) acc[d] = fmaf(p, Vs[j][d], acc[d]);
        }
        m = m_new;
        __syncthreads();
    }

    const float inv_l = 1.0f / l;
    __nv_bfloat16* hp = g_att_hi + ((size_t)batch * N2_ + qi) * INNER_ + head * DH_;
    __nv_bfloat16* lp = g_att_lo + ((size_t)batch * N2_ + qi) * INNER_ + head * DH_;
    #pragma unroll
    for (int d = 0; d < DH_; d += 2) {
        __nv_bfloat16 h0,l0,h1,l1;
        split_hl(acc[d] * inv_l, h0, l0);
        split_hl(acc[d+1] * inv_l, h1, l1);
        *reinterpret_cast<__nv_bfloat162*>(hp + d) = __nv_bfloat162(h0, h1);
        *reinterpret_cast<__nv_bfloat162*>(lp + d) = __nv_bfloat162(l0, l1);
    }
}

// ---------------- launch ----------------
extern "C" void kernel_launch(void* const* d_in, const int* in_sizes, int n_in,
                              void* d_out, int out_size)
{
    const float* x       = (const float*)d_in[0];
    const float* latents = (const float*)d_in[1];
    const float* shift   = (const float*)d_in[2];
    const float* scale   = (const float*)d_in[3];
    const float* ln1w    = (const float*)d_in[4];
    const float* ln1b    = (const float*)d_in[5];
    const float* ln2w    = (const float*)d_in[6];
    const float* ln2b    = (const float*)d_in[7];
    const float* Wq      = (const float*)d_in[8];
    const float* Wkv     = (const float*)d_in[9];
    const float* Wo      = (const float*)d_in[10];
    float* out = (float*)d_out;

    __nv_bfloat16 *kvin_h, *kvin_l, *latm_h, *latm_l;
    __nv_bfloat16 *wq_h, *wq_l, *wkv_h, *wkv_l, *wo_h, *wo_l, *att_h, *att_l;
    float *qb, *kvb;
    cudaGetSymbolAddress((void**)&kvin_h, g_kvin_hi);
    cudaGetSymbolAddress((void**)&kvin_l, g_kvin_lo);
    cudaGetSymbolAddress((void**)&latm_h, g_latm_hi);
    cudaGetSymbolAddress((void**)&latm_l, g_latm_lo);
    cudaGetSymbolAddress((void**)&wq_h, g_wq_hi);
    cudaGetSymbolAddress((void**)&wq_l, g_wq_lo);
    cudaGetSymbolAddress((void**)&wkv_h, g_wkv_hi);
    cudaGetSymbolAddress((void**)&wkv_l, g_wkv_lo);
    cudaGetSymbolAddress((void**)&wo_h, g_wo_hi);
    cudaGetSymbolAddress((void**)&wo_l, g_wo_lo);
    cudaGetSymbolAddress((void**)&att_h, g_att_hi);
    cudaGetSymbolAddress((void**)&att_l, g_att_lo);
    cudaGetSymbolAddress((void**)&qb, g_q);
    cudaGetSymbolAddress((void**)&kvb, g_kv);

    cudaFuncSetAttribute(gemm_bf16x3, cudaFuncAttributeMaxDynamicSharedMemorySize, 2 * GS_STAGE);

    // 0) weight splits
    split_kernel<<<(INNER_ * D_ / 4 + 255) / 256, 256>>>(Wq, wq_h, wq_l, INNER_ * D_ / 4);
    split_kernel<<<(2 * INNER_ * D_ / 4 + 255) / 256, 256>>>(Wkv, wkv_h, wkv_l, 2 * INNER_ * D_ / 4);
    split_kernel<<<(D_ * INNER_ / 4 + 255) / 256, 256>>>(Wo, wo_h, wo_l, D_ * INNER_ / 4);

    // 1) LayerNorms + modulation (writes bf16 hi/lo)
    ln_kernel<<<B_ * L_, 256>>>(x, latents, shift, scale, ln1w, ln1b, ln2w, ln2b);

    // 2) q = latm @ Wq^T : M=2048, N=1024, K=1024
    {
        dim3 grid(INNER_ / 128, (B_ * N2_) / 128);
        gemm_bf16x3<<<grid, 256, 2 * GS_STAGE>>>(latm_h, latm_l, wq_h, wq_l, qb,
                                                 B_ * N2_, INNER_, D_);
    }
    // 3) kv = kvin @ Wkv^T : M=34816, N=2048, K=1024
    {
        dim3 grid((2 * INNER_) / 128, (B_ * L_) / 128);
        gemm_bf16x3<<<grid, 256, 2 * GS_STAGE>>>(kvin_h, kvin_l, wkv_h, wkv_l, kvb,
                                                 B_ * L_, 2 * INNER_, D_);
    }
    // 4) attention (fp32 SIMT, writes att as bf16 hi/lo)
    {
        dim3 grid(B_ * HEADS_, N2_ / 128);
        attn_kernel<<<grid, 128>>>();
    }
    // 5) out = att @ Wo^T : M=2048, N=1024, K=1024
    {
        dim3 grid(D_ / 128, (B_ * N2_) / 128);
        gemm_bf16x3<<<grid, 256, 2 * GS_STAGE>>>(att_h, att_l, wo_h, wo_l, out,
                                                 B_ * N2_, D_, INNER_);
    }
    (void)in_sizes; (void)n_in; (void)out_size;
}

// round 4
// speedup vs baseline: 1.5458x; 1.0012x over previous
#include <cuda_runtime.h>
#include <cuda_bf16.h>
#include <math.h>
#include <stdint.h>

#define B_   8
#define N1_  4096
#define N2_  256
#define D_   1024
#define INNER_ 1024
#define HEADS_ 16
#define DH_  64
#define L_   (N1_ + N2_)   // 4352
#define EPS_ 1e-5f

// ---------------- scratch (device globals; no runtime allocation) ----------------
__device__ __nv_bfloat16 g_kvin_hi[(size_t)B_ * L_ * D_];
__device__ __nv_bfloat16 g_kvin_lo[(size_t)B_ * L_ * D_];
__device__ __nv_bfloat16 g_latm_hi[(size_t)B_ * N2_ * D_];
__device__ __nv_bfloat16 g_latm_lo[(size_t)B_ * N2_ * D_];
__device__ __nv_bfloat16 g_wq_hi[(size_t)INNER_ * D_];
__device__ __nv_bfloat16 g_wq_lo[(size_t)INNER_ * D_];
__device__ __nv_bfloat16 g_wkv_hi[(size_t)2 * INNER_ * D_];
__device__ __nv_bfloat16 g_wkv_lo[(size_t)2 * INNER_ * D_];
__device__ __nv_bfloat16 g_wo_hi[(size_t)D_ * INNER_];
__device__ __nv_bfloat16 g_wo_lo[(size_t)D_ * INNER_];
__device__ __nv_bfloat16 g_att_hi[(size_t)B_ * N2_ * INNER_];
__device__ __nv_bfloat16 g_att_lo[(size_t)B_ * N2_ * INNER_];
__device__ float g_q [(size_t)B_ * N2_ * INNER_];
__device__ float g_kv[(size_t)B_ * L_ * 2 * INNER_];

// ============================ PTX helpers ============================
__device__ __forceinline__ uint32_t smem_u32(const void* p) {
    uint32_t a;
    asm("{ .reg .u64 t; cvta.to.shared.u64 t, %1; cvt.u32.u64 %0, t; }"
        : "=r"(a) : "l"(p));
    return a;
}

#define CP_ASYNC16(dst, src) \
    asm volatile("cp.async.cg.shared.global [%0], [%1], 16;" :: "r"(dst), "l"(src))
#define CP_COMMIT() asm volatile("cp.async.commit_group;" ::: "memory")
#define CP_WAIT(n)  asm volatile("cp.async.wait_group %0;" :: "n"(n) : "memory")

#define LDSM_X4(r, addr) \
    asm volatile("ldmatrix.sync.aligned.m8n8.x4.shared.b16 {%0,%1,%2,%3}, [%4];" \
                 : "=r"((r)[0]), "=r"((r)[1]), "=r"((r)[2]), "=r"((r)[3]) : "r"(addr))

#define MMA16816(acc, a, b0, b1) \
    asm volatile("mma.sync.aligned.m16n8k16.row.col.f32.bf16.bf16.f32 " \
        "{%0,%1,%2,%3}, {%4,%5,%6,%7}, {%8,%9}, {%0,%1,%2,%3};" \
        : "+f"((acc)[0]), "+f"((acc)[1]), "+f"((acc)[2]), "+f"((acc)[3]) \
        : "r"((a)[0]), "r"((a)[1]), "r"((a)[2]), "r"((a)[3]), "r"(b0), "r"(b1))

__device__ __forceinline__ void split_hl(float v, __nv_bfloat16& h, __nv_bfloat16& l) {
    h = __float2bfloat16_rn(v);
    l = __float2bfloat16_rn(v - __bfloat162float(h));
}

// ============================ bf16x3 mma.sync GEMM ============================
// C[M,N] = A[M,K] * W[N,K]^T with A,W given as bf16 (hi,lo) pairs; fp32 accumulate.
// Tile 128x128, BK=32, 2-stage cp.async pipeline, 256 threads (8 warps, 4x2).
// smem per stage: 4 arrays x 128 rows x 40 bf16 (pad) = 40960 B; 2 stages = 81920 B.
#define GS_STAGE 40960
#define GS_ARR   10240
#define GS_ROWB  80

__global__ __launch_bounds__(256, 1)
void gemm_bf16x3(const __nv_bfloat16* __restrict__ Ah, const __nv_bfloat16* __restrict__ Al,
                 const __nv_bfloat16* __restrict__ Bh, const __nv_bfloat16* __restrict__ Bl,
                 float* __restrict__ C, int M, int N, int K)
{
    extern __shared__ char smraw[];
    const uint32_t smbase = smem_u32(smraw);

    const int tid  = threadIdx.x;
    const int wid  = tid >> 5;
    const int lane = tid & 31;
    const int bm = blockIdx.y * 128;
    const int bn = blockIdx.x * 128;
    const int wm = (wid & 3) * 32;   // warp m-offset (4 warps down)
    const int wn = (wid >> 2) * 64;  // warp n-offset (2 warps across)

    const char* srcs[4] = { (const char*)Ah, (const char*)Al,
                            (const char*)Bh, (const char*)Bl };

    auto load_stage = [&](int kt, int st) {
        #pragma unroll
        for (int arr = 0; arr < 4; arr++) {
            const int rb = (arr < 2) ? bm : bn;
            #pragma unroll
            for (int j = 0; j < 2; j++) {
                const int ch  = tid * 2 + j;      // 0..511
                const int row = ch >> 2;
                const int col = ch & 3;
                const char* src = srcs[arr]
                    + ((size_t)(rb + row) * K + kt * 32) * 2 + col * 16;
                const uint32_t dst = smbase + st * GS_STAGE + arr * GS_ARR
                    + row * GS_ROWB + col * 16;
                CP_ASYNC16(dst, src);
            }
        }
    };

    float acc[2][8][4];
    #pragma unroll
    for (int i = 0; i < 2; i++)
        #pragma unroll
        for (int t = 0; t < 8; t++)
            #pragma unroll
            for (int c = 0; c < 4; c++) acc[i][t][c] = 0.f;

    const int niter = K / 32;
    load_stage(0, 0);
    CP_COMMIT();

    for (int kt = 0; kt < niter; kt++) {
        const int st = kt & 1;
        if (kt + 1 < niter) {
            load_stage(kt + 1, st ^ 1);
            CP_COMMIT();
            CP_WAIT(1);
        } else {
            CP_WAIT(0);
        }
        __syncthreads();

        const uint32_t base = smbase + st * GS_STAGE;
        #pragma unroll
        for (int kk = 0; kk < 2; kk++) {
            uint32_t ah[2][4], al[2][4], bh[4][4], bl[4][4];
            #pragma unroll
            for (int i = 0; i < 2; i++) {
                const uint32_t ra = base
                    + (uint32_t)((wm + i * 16 + (lane & 15)) * GS_ROWB
                                 + ((lane >> 4) << 4) + kk * 32);
                LDSM_X4(ah[i], ra);
                LDSM_X4(al[i], ra + GS_ARR);
            }
            #pragma unroll
            for (int g = 0; g < 4; g++) {
                const uint32_t rbb = base + 2 * GS_ARR
                    + (uint32_t)((wn + g * 16 + ((lane >> 4) << 3) + (lane & 7)) * GS_ROWB
                                 + (((lane >> 3) & 1) << 4) + kk * 32);
                LDSM_X4(bh[g], rbb);
                LDSM_X4(bl[g], rbb + GS_ARR);
            }
            #pragma unroll
            for (int i = 0; i < 2; i++) {
                #pragma unroll
                for (int g = 0; g < 4; g++) {
                    MMA16816(acc[i][2*g],   ah[i], bh[g][0], bh[g][1]);
                    MMA16816(acc[i][2*g],   ah[i], bl[g][0], bl[g][1]);
                    MMA16816(acc[i][2*g],   al[i], bh[g][0], bh[g][1]);
                    MMA16816(acc[i][2*g+1], ah[i], bh[g][2], bh[g][3]);
                    MMA16816(acc[i][2*g+1], ah[i], bl[g][2], bl[g][3]);
                    MMA16816(acc[i][2*g+1], al[i], bh[g][2], bh[g][3]);
                }
            }
        }
        __syncthreads();
    }

    // epilogue: c-frag rows (lane>>2, +8), cols 2*(lane&3)
    #pragma unroll
    for (int i = 0; i < 2; i++) {
        #pragma unroll
        for (int t = 0; t < 8; t++) {
            const int r0 = bm + wm + i * 16 + (lane >> 2);
            const int c  = bn + wn + t * 8 + (lane & 3) * 2;
            *reinterpret_cast<float2*>(&C[(size_t)r0 * N + c]) =
                make_float2(acc[i][t][0], acc[i][t][1]);
            *reinterpret_cast<float2*>(&C[(size_t)(r0 + 8) * N + c]) =
                make_float2(acc[i][t][2], acc[i][t][3]);
        }
    }
    (void)M;
}

// ---------------- weight split: fp32 -> bf16 hi/lo ----------------
__global__ __launch_bounds__(256)
void split_kernel(const float* __restrict__ src,
                  __nv_bfloat16* __restrict__ hi, __nv_bfloat16* __restrict__ lo, int n4)
{
    int i = blockIdx.x * blockDim.x + threadIdx.x;
    if (i >= n4) return;
    float4 v = reinterpret_cast<const float4*>(src)[i];
    __nv_bfloat16 h0,l0,h1,l1,h2,l2,h3,l3;
    split_hl(v.x, h0, l0); split_hl(v.y, h1, l1);
    split_hl(v.z, h2, l2); split_hl(v.w, h3, l3);
    __nv_bfloat162* hp = reinterpret_cast<__nv_bfloat162*>(hi);
    __nv_bfloat162* lp = reinterpret_cast<__nv_bfloat162*>(lo);
    hp[i*2]   = __nv_bfloat162(h0, h1);
    hp[i*2+1] = __nv_bfloat162(h2, h3);
    lp[i*2]   = __nv_bfloat162(l0, l1);
    lp[i*2+1] = __nv_bfloat162(l2, l3);
}

// ---------------- LayerNorm (+ modulation), writes bf16 hi/lo ----------------
__global__ __launch_bounds__(256)
void ln_kernel(const float* __restrict__ x, const float* __restrict__ latents,
               const float* __restrict__ shift, const float* __restrict__ scale,
               const float* __restrict__ ln1w, const float* __restrict__ ln1b,
               const float* __restrict__ ln2w, const float* __restrict__ ln2b)
{
    const int row   = blockIdx.x;
    const int batch = row / L_;
    const int local = row % L_;
    const bool is_lat = (local >= N1_);

    const float* src = is_lat
        ? latents + ((size_t)batch * N2_ + (local - N1_)) * D_
        : x       + ((size_t)batch * N1_ + local) * D_;

    const int t = threadIdx.x;
    float4 v = reinterpret_cast<const float4*>(src)[t];

    float s  = v.x + v.y + v.z + v.w;
    float sq = v.x*v.x + v.y*v.y + v.z*v.z + v.w*v.w;

    __shared__ float red[16];
    __shared__ float red2[16];
    for (int o = 16; o > 0; o >>= 1) {
        s  += __shfl_down_sync(0xffffffff, s,  o);
        sq += __shfl_down_sync(0xffffffff, sq, o);
    }
    int warp = t >> 5, lane = t & 31;
    if (lane == 0) { red[warp] = s; red2[warp] = sq; }
    __syncthreads();
    if (warp == 0) {
        s  = (lane < 8) ? red[lane]  : 0.f;
        sq = (lane < 8) ? red2[lane] : 0.f;
        for (int o = 4; o > 0; o >>= 1) {
            s  += __shfl_down_sync(0xffffffff, s,  o);
            sq += __shfl_down_sync(0xffffffff, sq, o);
        }
        if (lane == 0) { red[0] = s; red2[0] = sq; }
    }
    __syncthreads();
    const float mu   = red[0] * (1.0f / D_);
    const float var  = red2[0] * (1.0f / D_) - mu * mu;
    const float rstd = rsqrtf(var + EPS_);

    float4 w4, b4, out;
    if (is_lat) {
        w4 = reinterpret_cast<const float4*>(ln2w)[t];
        b4 = reinterpret_cast<const float4*>(ln2b)[t];
    } else {
        w4 = reinterpret_cast<const float4*>(ln1w)[t];
        b4 = reinterpret_cast<const float4*>(ln1b)[t];
    }
    out.x = (v.x - mu) * rstd * w4.x + b4.x;
    out.y = (v.y - mu) * rstd * w4.y + b4.y;
    out.z = (v.z - mu) * rstd * w4.z + b4.z;
    out.w = (v.w - mu) * rstd * w4.w + b4.w;

    if (is_lat) {
        const float4 sc = reinterpret_cast<const float4*>(scale + (size_t)batch * D_)[t];
        const float4 sh = reinterpret_cast<const float4*>(shift + (size_t)batch * D_)[t];
        out.x = out.x * (1.0f + sc.x) + sh.x;
        out.y = out.y * (1.0f + sc.y) + sh.y;
        out.z = out.z * (1.0f + sc.z) + sh.z;
        out.w = out.w * (1.0f + sc.w) + sh.w;
    }

    __nv_bfloat16 h0,l0,h1,l1,h2,l2,h3,l3;
    split_hl(out.x, h0, l0); split_hl(out.y, h1, l1);
    split_hl(out.z, h2, l2); split_hl(out.w, h3, l3);
    __nv_bfloat162 hA(h0, h1), hB(h2, h3), lA(l0, l1), lB(l2, l3);

    {
        __nv_bfloat162* hp = reinterpret_cast<__nv_bfloat162*>(g_kvin_hi + (size_t)row * D_);
        __nv_bfloat162* lp = reinterpret_cast<__nv_bfloat162*>(g_kvin_lo + (size_t)row * D_);
        hp[t*2] = hA; hp[t*2+1] = hB;
        lp[t*2] = lA; lp[t*2+1] = lB;
    }
    if (is_lat) {
        const size_t lrow = (size_t)batch * N2_ + (local - N1_);
        __nv_bfloat162* hp = reinterpret_cast<__nv_bfloat162*>(g_latm_hi + lrow * D_);
        __nv_bfloat162* lp = reinterpret_cast<__nv_bfloat162*>(g_latm_lo + lrow * D_);
        hp[t*2] = hA; hp[t*2+1] = hB;
        lp[t*2] = lA; lp[t*2+1] = lB;
    }
}

// ---------------- Flash attention (fp32, online softmax) ----------------
#define TK 64
__global__ __launch_bounds__(128)
void attn_kernel()
{
    __shared__ float Ks[TK][DH_];
    __shared__ float Vs[TK][DH_];
    __shared__ float Sm[TK][128];

    const int bh    = blockIdx.x;
    const int batch = bh / HEADS_;
    const int head  = bh % HEADS_;
    const int tid   = threadIdx.x;
    const int qi    = blockIdx.y * 128 + tid;

    float q[DH_];
    {
        const float* qp = g_q + ((size_t)batch * N2_ + qi) * INNER_ + head * DH_;
        #pragma unroll
        for (int d = 0; d < DH_; d += 4) {
            float4 v = *reinterpret_cast<const float4*>(qp + d);
            q[d+0] = v.x * 0.125f; q[d+1] = v.y * 0.125f;
            q[d+2] = v.z * 0.125f; q[d+3] = v.w * 0.125f;
        }
    }

    float m = -INFINITY, l = 0.f;
    float acc[DH_];
    #pragma unroll
    for (int d = 0; d < DH_; d++) acc[d] = 0.f;

    const int lrow  = tid >> 1;
    const int lpart = (tid & 1) * 32;
    const size_t kvrow_base = (size_t)batch * L_;

    for (int t = 0; t < L_ / TK; t++) {
        {
            const int key = t * TK + lrow;
            const float* kp = g_kv + (kvrow_base + key) * (2 * INNER_) + head * DH_ + lpart;
            const float* vp = kp + INNER_;
            #pragma unroll
            for (int i = 0; i < 8; i++) {
                float4 kv4 = *reinterpret_cast<const float4*>(kp + i * 4);
                *reinterpret_cast<float4*>(&Ks[lrow][lpart + i * 4]) = kv4;
                float4 vv4 = *reinterpret_cast<const float4*>(vp + i * 4);
                *reinterpret_cast<float4*>(&Vs[lrow][lpart + i * 4]) = vv4;
            }
        }
        __syncthreads();

        float tm = -INFINITY;
        #pragma unroll 2
        for (int j = 0; j < TK; j++) {
            float s = 0.f;
            #pragma unroll
            for (int d = 0; d < DH_; d++) s = fmaf(q[d], Ks[j][d], s);
            Sm[j][tid] = s;
            tm = fmaxf(tm, s);
        }

        const float m_new = fmaxf(m, tm);
        const float corr  = __expf(m - m_new);
        l *= corr;
        #pragma unroll
        for (int d = 0; d < DH_; d++) acc[d] *= corr;

        #pragma unroll 2
        for (int j = 0; j < TK; j++) {
            float p = __expf(Sm[j][tid] - m_new);
            l += p;
            #pragma unroll
            for (int d = 0; d < DH_; d++) acc[d] = fmaf(p, Vs[j][d], acc[d]);
        }
        m = m_new;
        __syncthreads();
    }

    const float inv_l = 1.0f / l;
    __nv_bfloat16* hp = g_att_hi + ((size_t)batch * N2_ + qi) * INNER_ + head * DH_;
    __nv_bfloat16* lp = g_att_lo + ((size_t)batch * N2_ + qi) * INNER_ + head * DH_;
    #pragma unroll
    for (int d = 0; d < DH_; d += 2) {
        __nv_bfloat16 h0,l0,h1,l1;
        split_hl(acc[d] * inv_l, h0, l0);
        split_hl(acc[d+1] * inv_l, h1, l1);
        *reinterpret_cast<__nv_bfloat162*>(hp + d) = __nv_bfloat162(h0, h1);
        *reinterpret_cast<__nv_bfloat162*>(lp + d) = __nv_bfloat162(l0, l1);
    }
}

// ---------------- launch ----------------
extern "C" void kernel_launch(void* const* d_in, const int* in_sizes, int n_in,
                              void* d_out, int out_size)
{
    const float* x       = (const float*)d_in[0];
    const float* latents = (const float*)d_in[1];
    const float* shift   = (const float*)d_in[2];
    const float* scale   = (const float*)d_in[3];
    const float* ln1w    = (const float*)d_in[4];
    const float* ln1b    = (const float*)d_in[5];
    const float* ln2w    = (const float*)d_in[6];
    const float* ln2b    = (const float*)d_in[7];
    const float* Wq      = (const float*)d_in[8];
    const float* Wkv     = (const float*)d_in[9];
    const float* Wo      = (const float*)d_in[10];
    float* out = (float*)d_out;

    __nv_bfloat16 *kvin_h, *kvin_l, *latm_h, *latm_l;
    __nv_bfloat16 *wq_h, *wq_l, *wkv_h, *wkv_l, *wo_h, *wo_l, *att_h, *att_l;
    float *qb, *kvb;
    cudaGetSymbolAddress((void**)&kvin_h, g_kvin_hi);
    cudaGetSymbolAddress((void**)&kvin_l, g_kvin_lo);
    cudaGetSymbolAddress((void**)&latm_h, g_latm_hi);
    cudaGetSymbolAddress((void**)&latm_l, g_latm_lo);
    cudaGetSymbolAddress((void**)&wq_h, g_wq_hi);
    cudaGetSymbolAddress((void**)&wq_l, g_wq_lo);
    cudaGetSymbolAddress((void**)&wkv_h, g_wkv_hi);
    cudaGetSymbolAddress((void**)&wkv_l, g_wkv_lo);
    cudaGetSymbolAddress((void**)&wo_h, g_wo_hi);
    cudaGetSymbolAddress((void**)&wo_l, g_wo_lo);
    cudaGetSymbolAddress((void**)&att_h, g_att_hi);
    cudaGetSymbolAddress((void**)&att_l, g_att_lo);
    cudaGetSymbolAddress((void**)&qb, g_q);
    cudaGetSymbolAddress((void**)&kvb, g_kv);

    cudaFuncSetAttribute(gemm_bf16x3, cudaFuncAttributeMaxDynamicSharedMemorySize, 2 * GS_STAGE);

    // 0) weight splits
    split_kernel<<<(INNER_ * D_ / 4 + 255) / 256, 256>>>(Wq, wq_h, wq_l, INNER_ * D_ / 4);
    split_kernel<<<(2 * INNER_ * D_ / 4 + 255) / 256, 256>>>(Wkv, wkv_h, wkv_l, 2 * INNER_ * D_ / 4);
    split_kernel<<<(D_ * INNER_ / 4 + 255) / 256, 256>>>(Wo, wo_h, wo_l, D_ * INNER_ / 4);

    // 1) LayerNorms + modulation (writes bf16 hi/lo)
    ln_kernel<<<B_ * L_, 256>>>(x, latents, shift, scale, ln1w, ln1b, ln2w, ln2b);

    // 2) q = latm @ Wq^T : M=2048, N=1024, K=1024
    {
        dim3 grid(INNER_ / 128, (B_ * N2_) / 128);
        gemm_bf16x3<<<grid, 256, 2 * GS_STAGE>>>(latm_h, latm_l, wq_h, wq_l, qb,
                                                 B_ * N2_, INNER_, D_);
    }
    // 3) kv = kvin @ Wkv^T : M=34816, N=2048, K=1024
    {
        dim3 grid((2 * INNER_) / 128, (B_ * L_) / 128);
        gemm_bf16x3<<<grid, 256, 2 * GS_STAGE>>>(kvin_h, kvin_l, wkv_h, wkv_l, kvb,
                                                 B_ * L_, 2 * INNER_, D_);
    }
    // 4) attention (fp32 SIMT, writes att as bf16 hi/lo)
    {
        dim3 grid(B_ * HEADS_, N2_ / 128);
        attn_kernel<<<grid, 128>>>();
    }
    // 5) out = att @ Wo^T : M=2048, N=1024, K=1024
    {
        dim3 grid(D_ / 128, (B_ * N2_) / 128);
        gemm_bf16x3<<<grid, 256, 2 * GS_STAGE>>>(att_h, att_l, wo_h, wo_l, out,
                                                 B_ * N2_, D_, INNER_);
    }
    (void)in_sizes; (void)n_in; (void)out_size;
}

// round 5
// speedup vs baseline: 2.6962x; 1.7442x over previous
#include <cuda_runtime.h>
#include <cuda_bf16.h>
#include <cuda_fp16.h>
#include <math.h>
#include <stdint.h>

#define B_   8
#define N1_  4096
#define N2_  256
#define D_   1024
#define INNER_ 1024
#define HEADS_ 16
#define DH_  64
#define L_   (N1_ + N2_)
#define EPS_ 1e-5f

__device__ __nv_bfloat16 g_kvin_hi[(size_t)B_ * L_ * D_];
__device__ __nv_bfloat16 g_kvin_lo[(size_t)B_ * L_ * D_];
__device__ __nv_bfloat16 g_latm_hi[(size_t)B_ * N2_ * D_];
__device__ __nv_bfloat16 g_latm_lo[(size_t)B_ * N2_ * D_];
__device__ __nv_bfloat16 g_wq_hi[(size_t)INNER_ * D_];
__device__ __nv_bfloat16 g_wq_lo[(size_t)INNER_ * D_];
__device__ __nv_bfloat16 g_wkv_hi[(size_t)2 * INNER_ * D_];
__device__ __nv_bfloat16 g_wkv_lo[(size_t)2 * INNER_ * D_];
__device__ __nv_bfloat16 g_wo_hi[(size_t)D_ * INNER_];
__device__ __nv_bfloat16 g_wo_lo[(size_t)D_ * INNER_];
__device__ __nv_bfloat16 g_att_hi[(size_t)B_ * N2_ * INNER_];
__device__ __nv_bfloat16 g_att_lo[(size_t)B_ * N2_ * INNER_];
__device__ __nv_bfloat16 g_q_hi[(size_t)B_ * N2_ * INNER_];
__device__ __nv_bfloat16 g_q_lo[(size_t)B_ * N2_ * INNER_];
__device__ __nv_bfloat16 g_k_hi[(size_t)B_ * L_ * INNER_];
__device__ __nv_bfloat16 g_k_lo[(size_t)B_ * L_ * INNER_];
__device__ __half        g_v16 [(size_t)B_ * L_ * INNER_];

__device__ __forceinline__ uint32_t smem_u32(const void* p) {
    uint32_t a;
    asm("{ .reg .u64 t; cvta.to.shared.u64 t, %1; cvt.u32.u64 %0, t; }" : "=r"(a) : "l"(p));
    return a;
}
#define CP_ASYNC16(dst, src) \
    asm volatile("cp.async.cg.shared.global [%0], [%1], 16;" :: "r"(dst), "l"(src))
#define CP_COMMIT() asm volatile("cp.async.commit_group;" ::: "memory")
#define CP_WAIT(n)  asm volatile("cp.async.wait_group %0;" :: "n"(n) : "memory")
#define LDSM_X4(r, addr) \
    asm volatile("ldmatrix.sync.aligned.m8n8.x4.shared.b16 {%0,%1,%2,%3}, [%4];" \
                 : "=r"((r)[0]), "=r"((r)[1]), "=r"((r)[2]), "=r"((r)[3]) : "r"(addr))
#define LDSM_X4_T(r, addr) \
    asm volatile("ldmatrix.sync.aligned.m8n8.x4.trans.shared.b16 {%0,%1,%2,%3}, [%4];" \
                 : "=r"((r)[0]), "=r"((r)[1]), "=r"((r)[2]), "=r"((r)[3]) : "r"(addr))
#define MMA16816(acc, a, b0, b1) \
    asm volatile("mma.sync.aligned.m16n8k16.row.col.f32.bf16.bf16.f32 " \
        "{%0,%1,%2,%3}, {%4,%5,%6,%7}, {%8,%9}, {%0,%1,%2,%3};" \
        : "+f"((acc)[0]), "+f"((acc)[1]), "+f"((acc)[2]), "+f"((acc)[3]) \
        : "r"((a)[0]), "r"((a)[1]), "r"((a)[2]), "r"((a)[3]), "r"(b0), "r"(b1))
#define MMAF16(acc, a, b0, b1) \
    asm volatile("mma.sync.aligned.m16n8k16.row.col.f32.f16.f16.f32 " \
        "{%0,%1,%2,%3}, {%4,%5,%6,%7}, {%8,%9}, {%0,%1,%2,%3};" \
        : "+f"((acc)[0]), "+f"((acc)[1]), "+f"((acc)[2]), "+f"((acc)[3]) \
        : "r"((a)[0]), "r"((a)[1]), "r"((a)[2]), "r"((a)[3]), "r"(b0), "r"(b1))

__device__ __forceinline__ void split_hl(float v, __nv_bfloat16& h, __nv_bfloat16& l) {
    h = __float2bfloat16_rn(v);
    l = __float2bfloat16_rn(v - __bfloat162float(h));
}

// ============================ bf16x3 mma.sync GEMM ============================
// mode 0: fp32 C. mode 1: bf16 hi/lo (stride N). mode 2: cols<INNER -> hi/lo (stride INNER),
//         cols>=INNER -> fp16 V16 (stride INNER).
#define GS_STAGE 40960
#define GS_ARR   10240
#define GS_ROWB  80

__global__ __launch_bounds__(256, 1)
void gemm_bf16x3(const __nv_bfloat16* __restrict__ Ah, const __nv_bfloat16* __restrict__ Al,
                 const __nv_bfloat16* __restrict__ Bh, const __nv_bfloat16* __restrict__ Bl,
                 float* __restrict__ C,
                 __nv_bfloat16* __restrict__ Ch, __nv_bfloat16* __restrict__ Cl,
                 __half* __restrict__ V16, int N, int K, int mode)
{
    extern __shared__ char smraw[];
    const uint32_t smbase = smem_u32(smraw);
    const int tid = threadIdx.x, wid = tid >> 5, lane = tid & 31;
    const int bm = blockIdx.y * 128, bn = blockIdx.x * 128;
    const int wm = (wid & 3) * 32, wn = (wid >> 2) * 64;

    const char* srcs[4] = { (const char*)Ah, (const char*)Al, (const char*)Bh, (const char*)Bl };
    auto load_stage = [&](int kt, int st) {
        #pragma unroll
        for (int arr = 0; arr < 4; arr++) {
            const int rb = (arr < 2) ? bm : bn;
            #pragma unroll
            for (int j = 0; j < 2; j++) {
                const int ch = tid * 2 + j;
                const int row = ch >> 2, col = ch & 3;
                const char* src = srcs[arr] + ((size_t)(rb + row) * K + kt * 32) * 2 + col * 16;
                CP_ASYNC16(smbase + st * GS_STAGE + arr * GS_ARR + row * GS_ROWB + col * 16, src);
            }
        }
    };

    float acc[2][8][4];
    #pragma unroll
    for (int i = 0; i < 2; i++)
        #pragma unroll
        for (int t = 0; t < 8; t++)
            #pragma unroll
            for (int c = 0; c < 4; c++) acc[i][t][c] = 0.f;

    const int niter = K / 32;
    load_stage(0, 0);
    CP_COMMIT();

    for (int kt = 0; kt < niter; kt++) {
        const int st = kt & 1;
        if (kt + 1 < niter) { load_stage(kt + 1, st ^ 1); CP_COMMIT(); CP_WAIT(1); }
        else { CP_WAIT(0); }
        __syncthreads();

        const uint32_t base = smbase + st * GS_STAGE;
        #pragma unroll
        for (int kk = 0; kk < 2; kk++) {
            uint32_t ah[2][4], al[2][4], bh[4][4], bl[4][4];
            #pragma unroll
            for (int i = 0; i < 2; i++) {
                const uint32_t ra = base + (uint32_t)((wm + i * 16 + (lane & 15)) * GS_ROWB
                                    + ((lane >> 4) << 4) + kk * 32);
                LDSM_X4(ah[i], ra);
                LDSM_X4(al[i], ra + GS_ARR);
            }
            #pragma unroll
            for (int g = 0; g < 4; g++) {
                const uint32_t rb = base + 2 * GS_ARR
                    + (uint32_t)((wn + g * 16 + ((lane >> 4) << 3) + (lane & 7)) * GS_ROWB
                                 + (((lane >> 3) & 1) << 4) + kk * 32);
                LDSM_X4(bh[g], rb);
                LDSM_X4(bl[g], rb + GS_ARR);
            }
            #pragma unroll
            for (int i = 0; i < 2; i++)
                #pragma unroll
                for (int g = 0; g < 4; g++) {
                    MMA16816(acc[i][2*g],   ah[i], bh[g][0], bh[g][1]);
                    MMA16816(acc[i][2*g+1], ah[i], bh[g][2], bh[g][3]);
                }
            #pragma unroll
            for (int i = 0; i < 2; i++)
                #pragma unroll
                for (int g = 0; g < 4; g++) {
                    MMA16816(acc[i][2*g],   ah[i], bl[g][0], bl[g][1]);
                    MMA16816(acc[i][2*g+1], ah[i], bl[g][2], bl[g][3]);
                }
            #pragma unroll
            for (int i = 0; i < 2; i++)
                #pragma unroll
                for (int g = 0; g < 4; g++) {
                    MMA16816(acc[i][2*g],   al[i], bh[g][0], bh[g][1]);
                    MMA16816(acc[i][2*g+1], al[i], bh[g][2], bh[g][3]);
                }
        }
        __syncthreads();
    }

    #pragma unroll
    for (int i = 0; i < 2; i++)
        #pragma unroll
        for (int t = 0; t < 8; t++) {
            const int r0 = bm + wm + i * 16 + (lane >> 2);
            const int c  = bn + wn + t * 8 + (lane & 3) * 2;
            const float v0 = acc[i][t][0], v1 = acc[i][t][1];
            const float v2 = acc[i][t][2], v3 = acc[i][t][3];
            if (mode == 0) {
                *reinterpret_cast<float2*>(&C[(size_t)r0 * N + c]) = make_float2(v0, v1);
                *reinterpret_cast<float2*>(&C[(size_t)(r0 + 8) * N + c]) = make_float2(v2, v3);
            } else if (mode == 1 || c < INNER_) {
                const int sN = (mode == 1) ? N : INNER_;
                __nv_bfloat16 h0,o0,h1,o1,h2,o2,h3,o3;
                split_hl(v0,h0,o0); split_hl(v1,h1,o1); split_hl(v2,h2,o2); split_hl(v3,h3,o3);
                *reinterpret_cast<__nv_bfloat162*>(&Ch[(size_t)r0*sN + c]) = __nv_bfloat162(h0,h1);
                *reinterpret_cast<__nv_bfloat162*>(&Cl[(size_t)r0*sN + c]) = __nv_bfloat162(o0,o1);
                *reinterpret_cast<__nv_bfloat162*>(&Ch[(size_t)(r0+8)*sN + c]) = __nv_bfloat162(h2,h3);
                *reinterpret_cast<__nv_bfloat162*>(&Cl[(size_t)(r0+8)*sN + c]) = __nv_bfloat162(o2,o3);
            } else {
                const int cv = c - INNER_;
                *reinterpret_cast<__half2*>(&V16[(size_t)r0*INNER_ + cv]) = __floats2half2_rn(v0, v1);
                *reinterpret_cast<__half2*>(&V16[(size_t)(r0+8)*INNER_ + cv]) = __floats2half2_rn(v2, v3);
            }
        }
}

// ---------------- weight split ----------------
__global__ __launch_bounds__(256)
void split_kernel(const float* __restrict__ src, __nv_bfloat16* __restrict__ hi,
                  __nv_bfloat16* __restrict__ lo, int n4, float sc)
{
    int i = blockIdx.x * blockDim.x + threadIdx.x;
    if (i >= n4) return;
    float4 v = reinterpret_cast<const float4*>(src)[i];
    v.x *= sc; v.y *= sc; v.z *= sc; v.w *= sc;
    __nv_bfloat16 h0,l0,h1,l1,h2,l2,h3,l3;
    split_hl(v.x,h0,l0); split_hl(v.y,h1,l1); split_hl(v.z,h2,l2); split_hl(v.w,h3,l3);
    reinterpret_cast<__nv_bfloat162*>(hi)[i*2]   = __nv_bfloat162(h0,h1);
    reinterpret_cast<__nv_bfloat162*>(hi)[i*2+1] = __nv_bfloat162(h2,h3);
    reinterpret_cast<__nv_bfloat162*>(lo)[i*2]   = __nv_bfloat162(l0,l1);
    reinterpret_cast<__nv_bfloat162*>(lo)[i*2+1] = __nv_bfloat162(l2,l3);
}

// ---------------- LayerNorm (+ modulation) ----------------
__global__ __launch_bounds__(256)
void ln_kernel(const float* __restrict__ x, const float* __restrict__ latents,
               const float* __restrict__ shift, const float* __restrict__ scale,
               const float* __restrict__ ln1w, const float* __restrict__ ln1b,
               const float* __restrict__ ln2w, const float* __restrict__ ln2b)
{
    const int row = blockIdx.x, batch = row / L_, local = row % L_;
    const bool is_lat = (local >= N1_);
    const float* src = is_lat
        ? latents + ((size_t)batch * N2_ + (local - N1_)) * D_
        : x + ((size_t)batch * N1_ + local) * D_;

    const int t = threadIdx.x;
    float4 v = reinterpret_cast<const float4*>(src)[t];
    float s = v.x + v.y + v.z + v.w;
    float sq = v.x*v.x + v.y*v.y + v.z*v.z + v.w*v.w;

    __shared__ float red[16], red2[16];
    for (int o = 16; o > 0; o >>= 1) {
        s  += __shfl_down_sync(0xffffffff, s, o);
        sq += __shfl_down_sync(0xffffffff, sq, o);
    }
    int warp = t >> 5, lane = t & 31;
    if (lane == 0) { red[warp] = s; red2[warp] = sq; }
    __syncthreads();
    if (warp == 0) {
        s = (lane < 8) ? red[lane] : 0.f;
        sq = (lane < 8) ? red2[lane] : 0.f;
        for (int o = 4; o > 0; o >>= 1) {
            s  += __shfl_down_sync(0xffffffff, s, o);
            sq += __shfl_down_sync(0xffffffff, sq, o);
        }
        if (lane == 0) { red[0] = s; red2[0] = sq; }
    }
    __syncthreads();
    const float mu = red[0] * (1.0f / D_);
    const float var = red2[0] * (1.0f / D_) - mu * mu;
    const float rstd = rsqrtf(var + EPS_);

    float4 w4, b4, out;
    if (is_lat) {
        w4 = reinterpret_cast<const float4*>(ln2w)[t];
        b4 = reinterpret_cast<const float4*>(ln2b)[t];
    } else {
        w4 = reinterpret_cast<const float4*>(ln1w)[t];
        b4 = reinterpret_cast<const float4*>(ln1b)[t];
    }
    out.x = (v.x - mu) * rstd * w4.x + b4.x;
    out.y = (v.y - mu) * rstd * w4.y + b4.y;
    out.z = (v.z - mu) * rstd * w4.z + b4.z;
    out.w = (v.w - mu) * rstd * w4.w + b4.w;

    if (is_lat) {
        const float4 sc = reinterpret_cast<const float4*>(scale + (size_t)batch * D_)[t];
        const float4 sh = reinterpret_cast<const float4*>(shift + (size_t)batch * D_)[t];
        out.x = out.x * (1.0f + sc.x) + sh.x;
        out.y = out.y * (1.0f + sc.y) + sh.y;
        out.z = out.z * (1.0f + sc.z) + sh.z;
        out.w = out.w * (1.0f + sc.w) + sh.w;
    }

    __nv_bfloat16 h0,l0,h1,l1,h2,l2,h3,l3;
    split_hl(out.x,h0,l0); split_hl(out.y,h1,l1); split_hl(out.z,h2,l2); split_hl(out.w,h3,l3);
    __nv_bfloat162 hA(h0,h1), hB(h2,h3), lA(l0,l1), lB(l2,l3);
    {
        __nv_bfloat162* hp = reinterpret_cast<__nv_bfloat162*>(g_kvin_hi + (size_t)row * D_);
        __nv_bfloat162* lp = reinterpret_cast<__nv_bfloat162*>(g_kvin_lo + (size_t)row * D_);
        hp[t*2] = hA; hp[t*2+1] = hB; lp[t*2] = lA; lp[t*2+1] = lB;
    }
    if (is_lat) {
        const size_t lr = (size_t)batch * N2_ + (local - N1_);
        __nv_bfloat162* hp = reinterpret_cast<__nv_bfloat162*>(g_latm_hi + lr * D_);
        __nv_bfloat162* lp = reinterpret_cast<__nv_bfloat162*>(g_latm_lo + lr * D_);
        hp[t*2] = hA; hp[t*2+1] = hB; lp[t*2] = lA; lp[t*2+1] = lB;
    }
}

// ============================ mma.sync flash attention ============================
#define AT_ROWB 144
#define AQ_L 18432
#define AK_BASE 36864
#define AK_STAGE 27648
#define AKL 9216
#define AV 18432
#define A_SMEM 92160

__global__ __launch_bounds__(256, 1)
void attn_mma(const __nv_bfloat16* __restrict__ qh, const __nv_bfloat16* __restrict__ ql,
              const __nv_bfloat16* __restrict__ kh, const __nv_bfloat16* __restrict__ kl,
              const __half* __restrict__ v16,
              __nv_bfloat16* __restrict__ oh, __nv_bfloat16* __restrict__ ol)
{
    extern __shared__ char sm[];
    const uint32_t smb = smem_u32(sm);
    const int tid = threadIdx.x, wid = tid >> 5, lane = tid & 31;
    const int batch = blockIdx.x >> 4, head = blockIdx.x & 15;
    const int q0 = batch * N2_ + blockIdx.y * 128;
    const size_t kv0 = (size_t)batch * L_;

    for (int i = tid; i < 1024; i += 256) {
        const int row = i >> 3, ch = (i & 7) * 16;
        const size_t g = ((size_t)(q0 + row) * INNER_ + head * DH_) * 2;
        CP_ASYNC16(smb + row * AT_ROWB + ch, (const char*)qh + g + ch);
        CP_ASYNC16(smb + AQ_L + row * AT_ROWB + ch, (const char*)ql + g + ch);
    }
    CP_COMMIT();

    auto load_kv = [&](int t, int st) {
        const uint32_t sb = smb + AK_BASE + st * AK_STAGE;
        for (int i = tid; i < 512; i += 256) {
            const int row = i >> 3, ch = (i & 7) * 16;
            const size_t gr = kv0 + t * 64 + row;
            const size_t gk = (gr * INNER_ + head * DH_) * 2;
            CP_ASYNC16(sb + row * AT_ROWB + ch, (const char*)kh + gk + ch);
            CP_ASYNC16(sb + AKL + row * AT_ROWB + ch, (const char*)kl + gk + ch);
            CP_ASYNC16(sb + AV + row * AT_ROWB + ch, (const char*)v16 + gk + ch);
        }
        CP_COMMIT();
    };

    load_kv(0, 0);
    CP_WAIT(0);
    __syncthreads();

    uint32_t qfh[4][4], qfl[4][4];
    #pragma unroll
    for (int kk = 0; kk < 4; kk++) {
        const uint32_t ra = smb + (wid * 16 + (lane & 15)) * AT_ROWB + ((lane >> 4) << 4) + kk * 32;
        LDSM_X4(qfh[kk], ra);
        LDSM_X4(qfl[kk], ra + AQ_L);
    }

    float accO[8][4];
    #pragma unroll
    for (int nt = 0; nt < 8; nt++)
        #pragma unroll
        for (int c = 0; c < 4; c++) accO[nt][c] = 0.f;
    float m0 = -1e30f, m1 = -1e30f, l0 = 0.f, l1 = 0.f;

    const int NT = L_ / 64;
    for (int t = 0; t < NT; t++) {
        const int st = t & 1;
        if (t > 0) { CP_WAIT(0); __syncthreads(); }
        if (t + 1 < NT) load_kv(t + 1, st ^ 1);
        const uint32_t sb = smb + AK_BASE + st * AK_STAGE;

        float sacc[8][4];
        #pragma unroll
        for (int nt = 0; nt < 8; nt++)
            #pragma unroll
            for (int c = 0; c < 4; c++) sacc[nt][c] = 0.f;

        #pragma unroll
        for (int kk = 0; kk < 4; kk++) {
            uint32_t kbh[4][4], kbl[4][4];
            #pragma unroll
            for (int g = 0; g < 4; g++) {
                const uint32_t rb = sb + (g * 16 + ((lane >> 4) << 3) + (lane & 7)) * AT_ROWB
                                    + (((lane >> 3) & 1) << 4) + kk * 32;
                LDSM_X4(kbh[g], rb);
                LDSM_X4(kbl[g], rb + AKL);
            }
            #pragma unroll
            for (int g = 0; g < 4; g++) {
                MMA16816(sacc[2*g],   qfh[kk], kbh[g][0], kbh[g][1]);
                MMA16816(sacc[2*g+1], qfh[kk], kbh[g][2], kbh[g][3]);
            }
            #pragma unroll
            for (int g = 0; g < 4; g++) {
                MMA16816(sacc[2*g],   qfh[kk], kbl[g][0], kbl[g][1]);
                MMA16816(sacc[2*g+1], qfh[kk], kbl[g][2], kbl[g][3]);
            }
            #pragma unroll
            for (int g = 0; g < 4; g++) {
                MMA16816(sacc[2*g],   qfl[kk], kbh[g][0], kbh[g][1]);
                MMA16816(sacc[2*g+1], qfl[kk], kbh[g][2], kbh[g][3]);
            }
        }

        float tm0 = sacc[0][0], tm1 = sacc[0][2];
        #pragma unroll
        for (int nt = 0; nt < 8; nt++) {
            tm0 = fmaxf(tm0, fmaxf(sacc[nt][0], sacc[nt][1]));
            tm1 = fmaxf(tm1, fmaxf(sacc[nt][2], sacc[nt][3]));
        }
        tm0 = fmaxf(tm0, __shfl_xor_sync(0xffffffff, tm0, 1));
        tm0 = fmaxf(tm0, __shfl_xor_sync(0xffffffff, tm0, 2));
        tm1 = fmaxf(tm1, __shfl_xor_sync(0xffffffff, tm1, 1));
        tm1 = fmaxf(tm1, __shfl_xor_sync(0xffffffff, tm1, 2));

        const float mn0 = fmaxf(m0, tm0), mn1 = fmaxf(m1, tm1);
        const float c0 = exp2f(m0 - mn0), c1 = exp2f(m1 - mn1);
        m0 = mn0; m1 = mn1;

        float ls0 = 0.f, ls1 = 0.f;
        uint32_t pa[4][4];
        #pragma unroll
        for (int nt = 0; nt < 8; nt++) {
            const float p0 = exp2f(sacc[nt][0] - mn0);
            const float p1 = exp2f(sacc[nt][1] - mn0);
            const float p2 = exp2f(sacc[nt][2] - mn1);
            const float p3 = exp2f(sacc[nt][3] - mn1);
            ls0 += p0 + p1; ls1 += p2 + p3;
            __half2 ha = __floats2half2_rn(p0, p1);
            __half2 hb = __floats2half2_rn(p2, p3);
            pa[nt >> 1][(nt & 1) * 2 + 0] = *reinterpret_cast<uint32_t*>(&ha);
            pa[nt >> 1][(nt & 1) * 2 + 1] = *reinterpret_cast<uint32_t*>(&hb);
        }
        l0 = l0 * c0 + ls0;
        l1 = l1 * c1 + ls1;
        #pragma unroll
        for (int nt = 0; nt < 8; nt++) {
            accO[nt][0] *= c0; accO[nt][1] *= c0;
            accO[nt][2] *= c1; accO[nt][3] *= c1;
        }

        #pragma unroll
        for (int kt = 0; kt < 4; kt++) {
            uint32_t vb[4][4];
            #pragma unroll
            for (int g = 0; g < 4; g++) {
                const uint32_t rv = sb + AV + (kt * 16 + (lane & 15)) * AT_ROWB
                                    + g * 32 + ((lane >> 4) << 4);
                LDSM_X4_T(vb[g], rv);
            }
            #pragma unroll
            for (int g = 0; g < 4; g++) {
                MMAF16(accO[2*g],   pa[kt], vb[g][0], vb[g][1]);
                MMAF16(accO[2*g+1], pa[kt], vb[g][2], vb[g][3]);
            }
        }
    }

    l0 += __shfl_xor_sync(0xffffffff, l0, 1);
    l0 += __shfl_xor_sync(0xffffffff, l0, 2);
    l1 += __shfl_xor_sync(0xffffffff, l1, 1);
    l1 += __shfl_xor_sync(0xffffffff, l1, 2);
    const float i0 = 1.0f / l0, i1 = 1.0f / l1;

    const int qrow = q0 + wid * 16 + (lane >> 2);
    #pragma unroll
    for (int nt = 0; nt < 8; nt++) {
        const int col = head * DH_ + nt * 8 + (lane & 3) * 2;
        __nv_bfloat16 h0,lo0,h1,lo1,h2,lo2,h3,lo3;
        split_hl(accO[nt][0]*i0,h0,lo0); split_hl(accO[nt][1]*i0,h1,lo1);
        split_hl(accO[nt][2]*i1,h2,lo2); split_hl(accO[nt][3]*i1,h3,lo3);
        *reinterpret_cast<__nv_bfloat162*>(oh + (size_t)qrow*INNER_ + col) = __nv_bfloat162(h0,h1);
        *reinterpret_cast<__nv_bfloat162*>(ol + (size_t)qrow*INNER_ + col) = __nv_bfloat162(lo0,lo1);
        *reinterpret_cast<__nv_bfloat162*>(oh + (size_t)(qrow+8)*INNER_ + col) = __nv_bfloat162(h2,h3);
        *reinterpret_cast<__nv_bfloat162*>(ol + (size_t)(qrow+8)*INNER_ + col) = __nv_bfloat162(lo2,lo3);
    }
}

// ---------------- launch ----------------
extern "C" void kernel_launch(void* const* d_in, const int* in_sizes, int n_in,
                              void* d_out, int out_size)
{
    const float* x       = (const float*)d_in[0];
    const float* latents = (const float*)d_in[1];
    const float* shift   = (const float*)d_in[2];
    const float* scale   = (const float*)d_in[3];
    const float* ln1w    = (const float*)d_in[4];
    const float* ln1b    = (const float*)d_in[5];
    const float* ln2w    = (const float*)d_in[6];
    const float* ln2b    = (const float*)d_in[7];
    const float* Wq      = (const float*)d_in[8];
    const float* Wkv     = (const float*)d_in[9];
    const float* Wo      = (const float*)d_in[10];
    float* out = (float*)d_out;

    __nv_bfloat16 *kvin_h,*kvin_l,*latm_h,*latm_l,*wq_h,*wq_l,*wkv_h,*wkv_l,*wo_h,*wo_l;
    __nv_bfloat16 *att_h,*att_l,*q_h,*q_l,*k_h,*k_l;
    __half* v16;
    cudaGetSymbolAddress((void**)&kvin_h, g_kvin_hi);
    cudaGetSymbolAddress((void**)&kvin_l, g_kvin_lo);
    cudaGetSymbolAddress((void**)&latm_h, g_latm_hi);
    cudaGetSymbolAddress((void**)&latm_l, g_latm_lo);
    cudaGetSymbolAddress((void**)&wq_h, g_wq_hi);
    cudaGetSymbolAddress((void**)&wq_l, g_wq_lo);
    cudaGetSymbolAddress((void**)&wkv_h, g_wkv_hi);
    cudaGetSymbolAddress((void**)&wkv_l, g_wkv_lo);
    cudaGetSymbolAddress((void**)&wo_h, g_wo_hi);
    cudaGetSymbolAddress((void**)&wo_l, g_wo_lo);
    cudaGetSymbolAddress((void**)&att_h, g_att_hi);
    cudaGetSymbolAddress((void**)&att_l, g_att_lo);
    cudaGetSymbolAddress((void**)&q_h, g_q_hi);
    cudaGetSymbolAddress((void**)&q_l, g_q_lo);
    cudaGetSymbolAddress((void**)&k_h, g_k_hi);
    cudaGetSymbolAddress((void**)&k_l, g_k_lo);
    cudaGetSymbolAddress((void**)&v16, g_v16);

    cudaFuncSetAttribute(gemm_bf16x3, cudaFuncAttributeMaxDynamicSharedMemorySize, 2 * GS_STAGE);
    cudaFuncSetAttribute(attn_mma, cudaFuncAttributeMaxDynamicSharedMemorySize, A_SMEM);

    const float qsc = 0.125f * 1.44269504088896340736f;  // attn_scale^2 * log2(e)
    split_kernel<<<INNER_ * D_ / 1024, 256>>>(Wq, wq_h, wq_l, INNER_ * D_ / 4, qsc);
    split_kernel<<<2 * INNER_ * D_ / 1024, 256>>>(Wkv, wkv_h, wkv_l, 2 * INNER_ * D_ / 4, 1.0f);
    split_kernel<<<D_ * INNER_ / 1024, 256>>>(Wo, wo_h, wo_l, D_ * INNER_ / 4, 1.0f);

    ln_kernel<<<B_ * L_, 256>>>(x, latents, shift, scale, ln1w, ln1b, ln2w, ln2b);

    { // q (bf16 hi/lo out)
        dim3 grid(INNER_ / 128, (B_ * N2_) / 128);
        gemm_bf16x3<<<grid, 256, 2 * GS_STAGE>>>(latm_h, latm_l, wq_h, wq_l,
                                                 nullptr, q_h, q_l, nullptr, INNER_, D_, 1);
    }
    { // kv (K -> bf16 hi/lo, V -> fp16)
        dim3 grid((2 * INNER_) / 128, (B_ * L_) / 128);
        gemm_bf16x3<<<grid, 256, 2 * GS_STAGE>>>(kvin_h, kvin_l, wkv_h, wkv_l,
                                                 nullptr, k_h, k_l, v16, 2 * INNER_, D_, 2);
    }
    { // attention
        dim3 grid(B_ * HEADS_, N2_ / 128);
        attn_mma<<<grid, 256, A_SMEM>>>(q_h, q_l, k_h, k_l, v16, att_h, att_l);
    }
    { // out (fp32)
        dim3 grid(D_ / 128, (B_ * N2_) / 128);
        gemm_bf16x3<<<grid, 256, 2 * GS_STAGE>>>(att_h, att_l, wo_h, wo_l,
                                                 out, nullptr, nullptr, nullptr, D_, INNER_, 0);
    }
    (void)in_sizes; (void)n_in; (void)out_size;
}

// round 6
// speedup vs baseline: 3.5519x; 1.3174x over previous
#include <cuda_runtime.h>
#include <cuda_fp16.h>
#include <math.h>
#include <stdint.h>

#define B_   8
#define N1_  4096
#define N2_  256
#define D_   1024
#define INNER_ 1024
#define HEADS_ 16
#define DH_  64
#define L_   (N1_ + N2_)
#define EPS_ 1e-5f

__device__ __half g_kvin_hi[(size_t)B_ * L_ * D_];
__device__ __half g_kvin_lo[(size_t)B_ * L_ * D_];
__device__ __half g_latm_hi[(size_t)B_ * N2_ * D_];
__device__ __half g_latm_lo[(size_t)B_ * N2_ * D_];
__device__ __half g_wq16 [(size_t)INNER_ * D_];
__device__ __half g_wkv16[(size_t)2 * INNER_ * D_];
__device__ __half g_wo16 [(size_t)D_ * INNER_];
__device__ __half g_att_hi[(size_t)B_ * N2_ * INNER_];
__device__ __half g_att_lo[(size_t)B_ * N2_ * INNER_];
__device__ __half g_q_hi[(size_t)B_ * N2_ * INNER_];
__device__ __half g_q_lo[(size_t)B_ * N2_ * INNER_];
__device__ __half g_k_hi[(size_t)B_ * L_ * INNER_];
__device__ __half g_k_lo[(size_t)B_ * L_ * INNER_];
__device__ __half g_v16 [(size_t)B_ * L_ * INNER_];

__device__ __forceinline__ uint32_t smem_u32(const void* p) {
    uint32_t a;
    asm("{ .reg .u64 t; cvta.to.shared.u64 t, %1; cvt.u32.u64 %0, t; }" : "=r"(a) : "l"(p));
    return a;
}
#define CP_ASYNC16(dst, src) \
    asm volatile("cp.async.cg.shared.global [%0], [%1], 16;" :: "r"(dst), "l"(src))
#define CP_COMMIT() asm volatile("cp.async.commit_group;" ::: "memory")
#define CP_WAIT(n)  asm volatile("cp.async.wait_group %0;" :: "n"(n) : "memory")
#define LDSM_X4(r, addr) \
    asm volatile("ldmatrix.sync.aligned.m8n8.x4.shared.b16 {%0,%1,%2,%3}, [%4];" \
                 : "=r"((r)[0]), "=r"((r)[1]), "=r"((r)[2]), "=r"((r)[3]) : "r"(addr))
#define LDSM_X4_T(r, addr) \
    asm volatile("ldmatrix.sync.aligned.m8n8.x4.trans.shared.b16 {%0,%1,%2,%3}, [%4];" \
                 : "=r"((r)[0]), "=r"((r)[1]), "=r"((r)[2]), "=r"((r)[3]) : "r"(addr))
#define MMAF16(acc, a, b0, b1) \
    asm volatile("mma.sync.aligned.m16n8k16.row.col.f32.f16.f16.f32 " \
        "{%0,%1,%2,%3}, {%4,%5,%6,%7}, {%8,%9}, {%0,%1,%2,%3};" \
        : "+f"((acc)[0]), "+f"((acc)[1]), "+f"((acc)[2]), "+f"((acc)[3]) \
        : "r"((a)[0]), "r"((a)[1]), "r"((a)[2]), "r"((a)[3]), "r"(b0), "r"(b1))

__device__ __forceinline__ void split_hl(float v, __half& h, __half& l) {
    h = __float2half_rn(v);
    l = __float2half_rn(v - __half2float(h));
}

// ============================ fp16 2-pass mma.sync GEMM ============================
// C[M,N] = (Ah+Al)[M,K] * B16[N,K]^T, fp32 accumulate. A exact as fp16 hi/lo; B single fp16.
// mode 0: fp32 C. mode 1: fp16 hi/lo (stride N). mode 2: cols<INNER -> fp16 hi/lo (stride
// INNER); cols>=INNER -> fp16 single V16 (stride INNER).
#define GS_ARR   10240
#define GS_STAGE 30720
#define GS_ROWB  80

__global__ __launch_bounds__(256, 1)
void gemm_f16x2(const __half* __restrict__ Ah, const __half* __restrict__ Al,
                const __half* __restrict__ Bh,
                float* __restrict__ C,
                __half* __restrict__ Ch, __half* __restrict__ Cl,
                __half* __restrict__ V16, int N, int K, int mode)
{
    extern __shared__ char smraw[];
    const uint32_t smbase = smem_u32(smraw);
    const int tid = threadIdx.x, wid = tid >> 5, lane = tid & 31;
    const int bm = blockIdx.y * 128, bn = blockIdx.x * 128;
    const int wm = (wid & 3) * 32, wn = (wid >> 2) * 64;

    const char* srcs[3] = { (const char*)Ah, (const char*)Al, (const char*)Bh };
    auto load_stage = [&](int kt, int st) {
        #pragma unroll
        for (int arr = 0; arr < 3; arr++) {
            const int rb = (arr < 2) ? bm : bn;
            #pragma unroll
            for (int j = 0; j < 2; j++) {
                const int ch = tid * 2 + j;
                const int row = ch >> 2, col = ch & 3;
                const char* src = srcs[arr] + ((size_t)(rb + row) * K + kt * 32) * 2 + col * 16;
                CP_ASYNC16(smbase + st * GS_STAGE + arr * GS_ARR + row * GS_ROWB + col * 16, src);
            }
        }
    };

    float acc[2][8][4];
    #pragma unroll
    for (int i = 0; i < 2; i++)
        #pragma unroll
        for (int t = 0; t < 8; t++)
            #pragma unroll
            for (int c = 0; c < 4; c++) acc[i][t][c] = 0.f;

    const int niter = K / 32;
    load_stage(0, 0);
    CP_COMMIT();

    for (int kt = 0; kt < niter; kt++) {
        const int st = kt & 1;
        if (kt + 1 < niter) { load_stage(kt + 1, st ^ 1); CP_COMMIT(); CP_WAIT(1); }
        else { CP_WAIT(0); }
        __syncthreads();

        const uint32_t base = smbase + st * GS_STAGE;
        #pragma unroll
        for (int kk = 0; kk < 2; kk++) {
            uint32_t ah[2][4], al[2][4], bb[4][4];
            #pragma unroll
            for (int i = 0; i < 2; i++) {
                const uint32_t ra = base + (uint32_t)((wm + i * 16 + (lane & 15)) * GS_ROWB
                                    + ((lane >> 4) << 4) + kk * 32);
                LDSM_X4(ah[i], ra);
                LDSM_X4(al[i], ra + GS_ARR);
            }
            #pragma unroll
            for (int g = 0; g < 4; g++) {
                const uint32_t rb = base + 2 * GS_ARR
                    + (uint32_t)((wn + g * 16 + ((lane >> 4) << 3) + (lane & 7)) * GS_ROWB
                                 + (((lane >> 3) & 1) << 4) + kk * 32);
                LDSM_X4(bb[g], rb);
            }
            #pragma unroll
            for (int i = 0; i < 2; i++)
                #pragma unroll
                for (int g = 0; g < 4; g++) {
                    MMAF16(acc[i][2*g],   ah[i], bb[g][0], bb[g][1]);
                    MMAF16(acc[i][2*g+1], ah[i], bb[g][2], bb[g][3]);
                }
            #pragma unroll
            for (int i = 0; i < 2; i++)
                #pragma unroll
                for (int g = 0; g < 4; g++) {
                    MMAF16(acc[i][2*g],   al[i], bb[g][0], bb[g][1]);
                    MMAF16(acc[i][2*g+1], al[i], bb[g][2], bb[g][3]);
                }
        }
        __syncthreads();
    }

    #pragma unroll
    for (int i = 0; i < 2; i++)
        #pragma unroll
        for (int t = 0; t < 8; t++) {
            const int r0 = bm + wm + i * 16 + (lane >> 2);
            const int c  = bn + wn + t * 8 + (lane & 3) * 2;
            const float v0 = acc[i][t][0], v1 = acc[i][t][1];
            const float v2 = acc[i][t][2], v3 = acc[i][t][3];
            if (mode == 0) {
                *reinterpret_cast<float2*>(&C[(size_t)r0 * N + c]) = make_float2(v0, v1);
                *reinterpret_cast<float2*>(&C[(size_t)(r0 + 8) * N + c]) = make_float2(v2, v3);
            } else if (mode == 1 || c < INNER_) {
                const int sN = (mode == 1) ? N : INNER_;
                __half h0,o0,h1,o1,h2,o2,h3,o3;
                split_hl(v0,h0,o0); split_hl(v1,h1,o1); split_hl(v2,h2,o2); split_hl(v3,h3,o3);
                *reinterpret_cast<__half2*>(&Ch[(size_t)r0*sN + c]) = __half2(h0,h1);
                *reinterpret_cast<__half2*>(&Cl[(size_t)r0*sN + c]) = __half2(o0,o1);
                *reinterpret_cast<__half2*>(&Ch[(size_t)(r0+8)*sN + c]) = __half2(h2,h3);
                *reinterpret_cast<__half2*>(&Cl[(size_t)(r0+8)*sN + c]) = __half2(o2,o3);
            } else {
                const int cv = c - INNER_;
                *reinterpret_cast<__half2*>(&V16[(size_t)r0*INNER_ + cv]) = __floats2half2_rn(v0, v1);
                *reinterpret_cast<__half2*>(&V16[(size_t)(r0+8)*INNER_ + cv]) = __floats2half2_rn(v2, v3);
            }
        }
}

// ---------------- weight convert: fp32 -> fp16 (scaled) ----------------
__global__ __launch_bounds__(256)
void conv_kernel(const float* __restrict__ src, __half* __restrict__ dst, int n4, float sc)
{
    int i = blockIdx.x * blockDim.x + threadIdx.x;
    if (i >= n4) return;
    float4 v = reinterpret_cast<const float4*>(src)[i];
    reinterpret_cast<__half2*>(dst)[i*2]   = __floats2half2_rn(v.x * sc, v.y * sc);
    reinterpret_cast<__half2*>(dst)[i*2+1] = __floats2half2_rn(v.z * sc, v.w * sc);
}

// ---------------- LayerNorm (+ modulation), writes fp16 hi/lo ----------------
__global__ __launch_bounds__(256)
void ln_kernel(const float* __restrict__ x, const float* __restrict__ latents,
               const float* __restrict__ shift, const float* __restrict__ scale,
               const float* __restrict__ ln1w, const float* __restrict__ ln1b,
               const float* __restrict__ ln2w, const float* __restrict__ ln2b)
{
    const int row = blockIdx.x, batch = row / L_, local = row % L_;
    const bool is_lat = (local >= N1_);
    const float* src = is_lat
        ? latents + ((size_t)batch * N2_ + (local - N1_)) * D_
        : x + ((size_t)batch * N1_ + local) * D_;

    const int t = threadIdx.x;
    float4 v = reinterpret_cast<const float4*>(src)[t];
    float s = v.x + v.y + v.z + v.w;
    float sq = v.x*v.x + v.y*v.y + v.z*v.z + v.w*v.w;

    __shared__ float red[16], red2[16];
    for (int o = 16; o > 0; o >>= 1) {
        s  += __shfl_down_sync(0xffffffff, s, o);
        sq += __shfl_down_sync(0xffffffff, sq, o);
    }
    int warp = t >> 5, lane = t & 31;
    if (lane == 0) { red[warp] = s; red2[warp] = sq; }
    __syncthreads();
    if (warp == 0) {
        s = (lane < 8) ? red[lane] : 0.f;
        sq = (lane < 8) ? red2[lane] : 0.f;
        for (int o = 4; o > 0; o >>= 1) {
            s  += __shfl_down_sync(0xffffffff, s, o);
            sq += __shfl_down_sync(0xffffffff, sq, o);
        }
        if (lane == 0) { red[0] = s; red2[0] = sq; }
    }
    __syncthreads();
    const float mu = red[0] * (1.0f / D_);
    const float var = red2[0] * (1.0f / D_) - mu * mu;
    const float rstd = rsqrtf(var + EPS_);

    float4 w4, b4, out;
    if (is_lat) {
        w4 = reinterpret_cast<const float4*>(ln2w)[t];
        b4 = reinterpret_cast<const float4*>(ln2b)[t];
    } else {
        w4 = reinterpret_cast<const float4*>(ln1w)[t];
        b4 = reinterpret_cast<const float4*>(ln1b)[t];
    }
    out.x = (v.x - mu) * rstd * w4.x + b4.x;
    out.y = (v.y - mu) * rstd * w4.y + b4.y;
    out.z = (v.z - mu) * rstd * w4.z + b4.z;
    out.w = (v.w - mu) * rstd * w4.w + b4.w;

    if (is_lat) {
        const float4 sc = reinterpret_cast<const float4*>(scale + (size_t)batch * D_)[t];
        const float4 sh = reinterpret_cast<const float4*>(shift + (size_t)batch * D_)[t];
        out.x = out.x * (1.0f + sc.x) + sh.x;
        out.y = out.y * (1.0f + sc.y) + sh.y;
        out.z = out.z * (1.0f + sc.z) + sh.z;
        out.w = out.w * (1.0f + sc.w) + sh.w;
    }

    __half h0,l0,h1,l1,h2,l2,h3,l3;
    split_hl(out.x,h0,l0); split_hl(out.y,h1,l1); split_hl(out.z,h2,l2); split_hl(out.w,h3,l3);
    __half2 hA(h0,h1), hB(h2,h3), lA(l0,l1), lB(l2,l3);
    {
        __half2* hp = reinterpret_cast<__half2*>(g_kvin_hi + (size_t)row * D_);
        __half2* lp = reinterpret_cast<__half2*>(g_kvin_lo + (size_t)row * D_);
        hp[t*2] = hA; hp[t*2+1] = hB; lp[t*2] = lA; lp[t*2+1] = lB;
    }
    if (is_lat) {
        const size_t lr = (size_t)batch * N2_ + (local - N1_);
        __half2* hp = reinterpret_cast<__half2*>(g_latm_hi + lr * D_);
        __half2* lp = reinterpret_cast<__half2*>(g_latm_lo + lr * D_);
        hp[t*2] = hA; hp[t*2+1] = hB; lp[t*2] = lA; lp[t*2+1] = lB;
    }
}

// ============================ mma.sync flash attention ============================
#define AT_ROWB 144
#define AQ_L 18432
#define AK_BASE 36864
#define AK_STAGE 27648
#define AKL 9216
#define AV 18432
#define A_SMEM 92160

__global__ __launch_bounds__(256, 1)
void attn_mma(const __half* __restrict__ qh, const __half* __restrict__ ql,
              const __half* __restrict__ kh, const __half* __restrict__ kl,
              const __half* __restrict__ v16,
              __half* __restrict__ oh, __half* __restrict__ ol)
{
    extern __shared__ char sm[];
    const uint32_t smb = smem_u32(sm);
    const int tid = threadIdx.x, wid = tid >> 5, lane = tid & 31;
    const int batch = blockIdx.x >> 4, head = blockIdx.x & 15;
    const int q0 = batch * N2_ + blockIdx.y * 128;
    const size_t kv0 = (size_t)batch * L_;

    for (int i = tid; i < 1024; i += 256) {
        const int row = i >> 3, ch = (i & 7) * 16;
        const size_t g = ((size_t)(q0 + row) * INNER_ + head * DH_) * 2;
        CP_ASYNC16(smb + row * AT_ROWB + ch, (const char*)qh + g + ch);
        CP_ASYNC16(smb + AQ_L + row * AT_ROWB + ch, (const char*)ql + g + ch);
    }
    CP_COMMIT();

    auto load_kv = [&](int t, int st) {
        const uint32_t sb = smb + AK_BASE + st * AK_STAGE;
        for (int i = tid; i < 512; i += 256) {
            const int row = i >> 3, ch = (i & 7) * 16;
            const size_t gr = kv0 + t * 64 + row;
            const size_t gk = (gr * INNER_ + head * DH_) * 2;
            CP_ASYNC16(sb + row * AT_ROWB + ch, (const char*)kh + gk + ch);
            CP_ASYNC16(sb + AKL + row * AT_ROWB + ch, (const char*)kl + gk + ch);
            CP_ASYNC16(sb + AV + row * AT_ROWB + ch, (const char*)v16 + gk + ch);
        }
        CP_COMMIT();
    };

    load_kv(0, 0);
    CP_WAIT(0);
    __syncthreads();

    uint32_t qfh[4][4], qfl[4][4];
    #pragma unroll
    for (int kk = 0; kk < 4; kk++) {
        const uint32_t ra = smb + (wid * 16 + (lane & 15)) * AT_ROWB + ((lane >> 4) << 4) + kk * 32;
        LDSM_X4(qfh[kk], ra);
        LDSM_X4(qfl[kk], ra + AQ_L);
    }

    float accO[8][4];
    #pragma unroll
    for (int nt = 0; nt < 8; nt++)
        #pragma unroll
        for (int c = 0; c < 4; c++) accO[nt][c] = 0.f;
    float m0 = -1e30f, m1 = -1e30f, l0 = 0.f, l1 = 0.f;

    const int NT = L_ / 64;
    for (int t = 0; t < NT; t++) {
        const int st = t & 1;
        if (t > 0) { CP_WAIT(0); __syncthreads(); }
        if (t + 1 < NT) load_kv(t + 1, st ^ 1);
        const uint32_t sb = smb + AK_BASE + st * AK_STAGE;

        float sacc[8][4];
        #pragma unroll
        for (int nt = 0; nt < 8; nt++)
            #pragma unroll
            for (int c = 0; c < 4; c++) sacc[nt][c] = 0.f;

        #pragma unroll
        for (int kk = 0; kk < 4; kk++) {
            uint32_t kbh[4][4], kbl[4][4];
            #pragma unroll
            for (int g = 0; g < 4; g++) {
                const uint32_t rb = sb + (g * 16 + ((lane >> 4) << 3) + (lane & 7)) * AT_ROWB
                                    + (((lane >> 3) & 1) << 4) + kk * 32;
                LDSM_X4(kbh[g], rb);
                LDSM_X4(kbl[g], rb + AKL);
            }
            #pragma unroll
            for (int g = 0; g < 4; g++) {
                MMAF16(sacc[2*g],   qfh[kk], kbh[g][0], kbh[g][1]);
                MMAF16(sacc[2*g+1], qfh[kk], kbh[g][2], kbh[g][3]);
            }
            #pragma unroll
            for (int g = 0; g < 4; g++) {
                MMAF16(sacc[2*g],   qfh[kk], kbl[g][0], kbl[g][1]);
                MMAF16(sacc[2*g+1], qfh[kk], kbl[g][2], kbl[g][3]);
            }
            #pragma unroll
            for (int g = 0; g < 4; g++) {
                MMAF16(sacc[2*g],   qfl[kk], kbh[g][0], kbh[g][1]);
                MMAF16(sacc[2*g+1], qfl[kk], kbh[g][2], kbh[g][3]);
            }
        }

        float tm0 = sacc[0][0], tm1 = sacc[0][2];
        #pragma unroll
        for (int nt = 0; nt < 8; nt++) {
            tm0 = fmaxf(tm0, fmaxf(sacc[nt][0], sacc[nt][1]));
            tm1 = fmaxf(tm1, fmaxf(sacc[nt][2], sacc[nt][3]));
        }
        tm0 = fmaxf(tm0, __shfl_xor_sync(0xffffffff, tm0, 1));
        tm0 = fmaxf(tm0, __shfl_xor_sync(0xffffffff, tm0, 2));
        tm1 = fmaxf(tm1, __shfl_xor_sync(0xffffffff, tm1, 1));
        tm1 = fmaxf(tm1, __shfl_xor_sync(0xffffffff, tm1, 2));

        const float mn0 = fmaxf(m0, tm0), mn1 = fmaxf(m1, tm1);
        const float c0 = exp2f(m0 - mn0), c1 = exp2f(m1 - mn1);
        m0 = mn0; m1 = mn1;

        float ls0 = 0.f, ls1 = 0.f;
        uint32_t pa[4][4];
        #pragma unroll
        for (int nt = 0; nt < 8; nt++) {
            const float p0 = exp2f(sacc[nt][0] - mn0);
            const float p1 = exp2f(sacc[nt][1] - mn0);
            const float p2 = exp2f(sacc[nt][2] - mn1);
            const float p3 = exp2f(sacc[nt][3] - mn1);
            ls0 += p0 + p1; ls1 += p2 + p3;
            __half2 ha = __floats2half2_rn(p0, p1);
            __half2 hb = __floats2half2_rn(p2, p3);
            pa[nt >> 1][(nt & 1) * 2 + 0] = *reinterpret_cast<uint32_t*>(&ha);
            pa[nt >> 1][(nt & 1) * 2 + 1] = *reinterpret_cast<uint32_t*>(&hb);
        }
        l0 = l0 * c0 + ls0;
        l1 = l1 * c1 + ls1;
        #pragma unroll
        for (int nt = 0; nt < 8; nt++) {
            accO[nt][0] *= c0; accO[nt][1] *= c0;
            accO[nt][2] *= c1; accO[nt][3] *= c1;
        }

        #pragma unroll
        for (int kt = 0; kt < 4; kt++) {
            uint32_t vb[4][4];
            #pragma unroll
            for (int g = 0; g < 4; g++) {
                const uint32_t rv = sb + AV + (kt * 16 + (lane & 15)) * AT_ROWB
                                    + g * 32 + ((lane >> 4) << 4);
                LDSM_X4_T(vb[g], rv);
            }
            #pragma unroll
            for (int g = 0; g < 4; g++) {
                MMAF16(accO[2*g],   pa[kt], vb[g][0], vb[g][1]);
                MMAF16(accO[2*g+1], pa[kt], vb[g][2], vb[g][3]);
            }
        }
    }

    l0 += __shfl_xor_sync(0xffffffff, l0, 1);
    l0 += __shfl_xor_sync(0xffffffff, l0, 2);
    l1 += __shfl_xor_sync(0xffffffff, l1, 1);
    l1 += __shfl_xor_sync(0xffffffff, l1, 2);
    const float i0 = 1.0f / l0, i1 = 1.0f / l1;

    const int qrow = q0 + wid * 16 + (lane >> 2);
    #pragma unroll
    for (int nt = 0; nt < 8; nt++) {
        const int col = head * DH_ + nt * 8 + (lane & 3) * 2;
        __half h0,lo0,h1,lo1,h2,lo2,h3,lo3;
        split_hl(accO[nt][0]*i0,h0,lo0); split_hl(accO[nt][1]*i0,h1,lo1);
        split_hl(accO[nt][2]*i1,h2,lo2); split_hl(accO[nt][3]*i1,h3,lo3);
        *reinterpret_cast<__half2*>(oh + (size_t)qrow*INNER_ + col) = __half2(h0,h1);
        *reinterpret_cast<__half2*>(ol + (size_t)qrow*INNER_ + col) = __half2(lo0,lo1);
        *reinterpret_cast<__half2*>(oh + (size_t)(qrow+8)*INNER_ + col) = __half2(h2,h3);
        *reinterpret_cast<__half2*>(ol + (size_t)(qrow+8)*INNER_ + col) = __half2(lo2,lo3);
    }
}

// ---------------- launch ----------------
extern "C" void kernel_launch(void* const* d_in, const int* in_sizes, int n_in,
                              void* d_out, int out_size)
{
    const float* x       = (const float*)d_in[0];
    const float* latents = (const float*)d_in[1];
    const float* shift   = (const float*)d_in[2];
    const float* scale   = (const float*)d_in[3];
    const float* ln1w    = (const float*)d_in[4];
    const float* ln1b    = (const float*)d_in[5];
    const float* ln2w    = (const float*)d_in[6];
    const float* ln2b    = (const float*)d_in[7];
    const float* Wq      = (const float*)d_in[8];
    const float* Wkv     = (const float*)d_in[9];
    const float* Wo      = (const float*)d_in[10];
    float* out = (float*)d_out;

    __half *kvin_h,*kvin_l,*latm_h,*latm_l,*wq16,*wkv16,*wo16;
    __half *att_h,*att_l,*q_h,*q_l,*k_h,*k_l,*v16;
    cudaGetSymbolAddress((void**)&kvin_h, g_kvin_hi);
    cudaGetSymbolAddress((void**)&kvin_l, g_kvin_lo);
    cudaGetSymbolAddress((void**)&latm_h, g_latm_hi);
    cudaGetSymbolAddress((void**)&latm_l, g_latm_lo);
    cudaGetSymbolAddress((void**)&wq16, g_wq16);
    cudaGetSymbolAddress((void**)&wkv16, g_wkv16);
    cudaGetSymbolAddress((void**)&wo16, g_wo16);
    cudaGetSymbolAddress((void**)&att_h, g_att_hi);
    cudaGetSymbolAddress((void**)&att_l, g_att_lo);
    cudaGetSymbolAddress((void**)&q_h, g_q_hi);
    cudaGetSymbolAddress((void**)&q_l, g_q_lo);
    cudaGetSymbolAddress((void**)&k_h, g_k_hi);
    cudaGetSymbolAddress((void**)&k_l, g_k_lo);
    cudaGetSymbolAddress((void**)&v16, g_v16);

    cudaFuncSetAttribute(gemm_f16x2, cudaFuncAttributeMaxDynamicSharedMemorySize, 2 * GS_STAGE);
    cudaFuncSetAttribute(attn_mma, cudaFuncAttributeMaxDynamicSharedMemorySize, A_SMEM);

    const float qsc = 0.125f * 1.44269504088896340736f;  // attn_scale^2 * log2(e)
    conv_kernel<<<INNER_ * D_ / 1024, 256>>>(Wq, wq16, INNER_ * D_ / 4, qsc);
    conv_kernel<<<2 * INNER_ * D_ / 1024, 256>>>(Wkv, wkv16, 2 * INNER_ * D_ / 4, 1.0f);
    conv_kernel<<<D_ * INNER_ / 1024, 256>>>(Wo, wo16, D_ * INNER_ / 4, 1.0f);

    ln_kernel<<<B_ * L_, 256>>>(x, latents, shift, scale, ln1w, ln1b, ln2w, ln2b);

    { // q (fp16 hi/lo out)
        dim3 grid(INNER_ / 128, (B_ * N2_) / 128);
        gemm_f16x2<<<grid, 256, 2 * GS_STAGE>>>(latm_h, latm_l, wq16,
                                                nullptr, q_h, q_l, nullptr, INNER_, D_, 1);
    }
    { // kv (K -> fp16 hi/lo, V -> fp16)
        dim3 grid((2 * INNER_) / 128, (B_ * L_) / 128);
        gemm_f16x2<<<grid, 256, 2 * GS_STAGE>>>(kvin_h, kvin_l, wkv16,
                                                nullptr, k_h, k_l, v16, 2 * INNER_, D_, 2);
    }
    { // attention
        dim3 grid(B_ * HEADS_, N2_ / 128);
        attn_mma<<<grid, 256, A_SMEM>>>(q_h, q_l, k_h, k_l, v16, att_h, att_l);
    }
    { // out (fp32)
        dim3 grid(D_ / 128, (B_ * N2_) / 128);
        gemm_f16x2<<<grid, 256, 2 * GS_STAGE>>>(att_h, att_l, wo16,
                                                out, nullptr, nullptr, nullptr, D_, INNER_, 0);
    }
    (void)in_sizes; (void)n_in; (void)out_size;
}

// round 7
// speedup vs baseline: 3.9559x; 1.1137x over previous
#include <cuda_runtime.h>
#include <cuda_fp16.h>
#include <math.h>
#include <stdint.h>

#define B_   8
#define N1_  4096
#define N2_  256
#define D_   1024
#define INNER_ 1024
#define HEADS_ 16
#define DH_  64
#define L_   (N1_ + N2_)
#define EPS_ 1e-5f

__device__ __half g_kvin_hi[(size_t)B_ * L_ * D_];
__device__ __half g_kvin_lo[(size_t)B_ * L_ * D_];
__device__ __half g_latm_hi[(size_t)B_ * N2_ * D_];
__device__ __half g_latm_lo[(size_t)B_ * N2_ * D_];
__device__ __half g_wq16 [(size_t)INNER_ * D_];
__device__ __half g_wkv16[(size_t)2 * INNER_ * D_];
__device__ __half g_wo16 [(size_t)D_ * INNER_];
__device__ __half g_att_hi[(size_t)B_ * N2_ * INNER_];
__device__ __half g_att_lo[(size_t)B_ * N2_ * INNER_];
__device__ __half g_q_hi[(size_t)B_ * N2_ * INNER_];
__device__ __half g_q_lo[(size_t)B_ * N2_ * INNER_];
__device__ __half g_k_hi[(size_t)B_ * L_ * INNER_];
__device__ __half g_k_lo[(size_t)B_ * L_ * INNER_];
__device__ __half g_v16 [(size_t)B_ * L_ * INNER_];

__device__ __forceinline__ uint32_t smem_u32(const void* p) {
    uint32_t a;
    asm("{ .reg .u64 t; cvta.to.shared.u64 t, %1; cvt.u32.u64 %0, t; }" : "=r"(a) : "l"(p));
    return a;
}
#define CP_ASYNC16(dst, src) \
    asm volatile("cp.async.cg.shared.global [%0], [%1], 16;" :: "r"(dst), "l"(src))
#define CP_COMMIT() asm volatile("cp.async.commit_group;" ::: "memory")
#define CP_WAIT(n)  asm volatile("cp.async.wait_group %0;" :: "n"(n) : "memory")
#define LDSM_X4(r, addr) \
    asm volatile("ldmatrix.sync.aligned.m8n8.x4.shared.b16 {%0,%1,%2,%3}, [%4];" \
                 : "=r"((r)[0]), "=r"((r)[1]), "=r"((r)[2]), "=r"((r)[3]) : "r"(addr))
#define LDSM_X4_T(r, addr) \
    asm volatile("ldmatrix.sync.aligned.m8n8.x4.trans.shared.b16 {%0,%1,%2,%3}, [%4];" \
                 : "=r"((r)[0]), "=r"((r)[1]), "=r"((r)[2]), "=r"((r)[3]) : "r"(addr))
#define MMAF16(acc, a, b0, b1) \
    asm volatile("mma.sync.aligned.m16n8k16.row.col.f32.f16.f16.f32 " \
        "{%0,%1,%2,%3}, {%4,%5,%6,%7}, {%8,%9}, {%0,%1,%2,%3};" \
        : "+f"((acc)[0]), "+f"((acc)[1]), "+f"((acc)[2]), "+f"((acc)[3]) \
        : "r"((a)[0]), "r"((a)[1]), "r"((a)[2]), "r"((a)[3]), "r"(b0), "r"(b1))

__device__ __forceinline__ void split_hl(float v, __half& h, __half& l) {
    h = __float2half_rn(v);
    l = __float2half_rn(v - __half2float(h));
}

// ============================ fp16 mma.sync GEMM (NPASS=1|2) ============================
// C[M,N] = (Ah[+Al])[M,K] * B16[N,K]^T, fp32 acc. 128x128 tile, BK=32, 3-stage cp.async.
// mode 0: fp32 C. mode 1: fp16 hi/lo (Ch,Cl). mode 3: fp16 single (V16). all stride N.
#define GS_ARR   10240
#define GS_STAGE 30720
#define GS_ROWB  80

template<int NPASS>
__global__ __launch_bounds__(256, 1)
void gemm_f16(const __half* __restrict__ Ah, const __half* __restrict__ Al,
              const __half* __restrict__ Bh,
              float* __restrict__ C,
              __half* __restrict__ Ch, __half* __restrict__ Cl,
              __half* __restrict__ V16, int N, int K, int mode)
{
    extern __shared__ char smraw[];
    const uint32_t smbase = smem_u32(smraw);
    const int tid = threadIdx.x, wid = tid >> 5, lane = tid & 31;
    const int bm = blockIdx.y * 128, bn = blockIdx.x * 128;
    const int wm = (wid & 3) * 32, wn = (wid >> 2) * 64;

    const char* srcs[3] = { (const char*)Ah, (const char*)Al, (const char*)Bh };
    auto load_stage = [&](int kt, int st) {
        #pragma unroll
        for (int arr = 0; arr < 3; arr++) {
            if (NPASS == 1 && arr == 1) continue;
            const int rb = (arr < 2) ? bm : bn;
            #pragma unroll
            for (int j = 0; j < 2; j++) {
                const int ch = tid * 2 + j;
                const int row = ch >> 2, col = ch & 3;
                const char* src = srcs[arr] + ((size_t)(rb + row) * K + kt * 32) * 2 + col * 16;
                CP_ASYNC16(smbase + st * GS_STAGE + arr * GS_ARR + row * GS_ROWB + col * 16, src);
            }
        }
        CP_COMMIT();
    };

    float acc[2][8][4];
    #pragma unroll
    for (int i = 0; i < 2; i++)
        #pragma unroll
        for (int t = 0; t < 8; t++)
            #pragma unroll
            for (int c = 0; c < 4; c++) acc[i][t][c] = 0.f;

    const int niter = K / 32;
    load_stage(0, 0);
    if (niter > 1) load_stage(1, 1);

    for (int kt = 0; kt < niter; kt++) {
        const int st = kt % 3;
        CP_WAIT(1);
        __syncthreads();
        if (kt + 2 < niter) load_stage(kt + 2, (kt + 2) % 3);

        const uint32_t base = smbase + st * GS_STAGE;
        #pragma unroll
        for (int kk = 0; kk < 2; kk++) {
            uint32_t ah[2][4], al[2][4], bb[4][4];
            #pragma unroll
            for (int i = 0; i < 2; i++) {
                const uint32_t ra = base + (uint32_t)((wm + i * 16 + (lane & 15)) * GS_ROWB
                                    + ((lane >> 4) << 4) + kk * 32);
                LDSM_X4(ah[i], ra);
                if (NPASS == 2) LDSM_X4(al[i], ra + GS_ARR);
            }
            #pragma unroll
            for (int g = 0; g < 4; g++) {
                const uint32_t rb = base + 2 * GS_ARR
                    + (uint32_t)((wn + g * 16 + ((lane >> 4) << 3) + (lane & 7)) * GS_ROWB
                                 + (((lane >> 3) & 1) << 4) + kk * 32);
                LDSM_X4(bb[g], rb);
            }
            #pragma unroll
            for (int i = 0; i < 2; i++)
                #pragma unroll
                for (int g = 0; g < 4; g++) {
                    MMAF16(acc[i][2*g],   ah[i], bb[g][0], bb[g][1]);
                    MMAF16(acc[i][2*g+1], ah[i], bb[g][2], bb[g][3]);
                }
            if (NPASS == 2) {
                #pragma unroll
                for (int i = 0; i < 2; i++)
                    #pragma unroll
                    for (int g = 0; g < 4; g++) {
                        MMAF16(acc[i][2*g],   al[i], bb[g][0], bb[g][1]);
                        MMAF16(acc[i][2*g+1], al[i], bb[g][2], bb[g][3]);
                    }
            }
        }
        __syncthreads();
    }

    #pragma unroll
    for (int i = 0; i < 2; i++)
        #pragma unroll
        for (int t = 0; t < 8; t++) {
            const int r0 = bm + wm + i * 16 + (lane >> 2);
            const int c  = bn + wn + t * 8 + (lane & 3) * 2;
            const float v0 = acc[i][t][0], v1 = acc[i][t][1];
            const float v2 = acc[i][t][2], v3 = acc[i][t][3];
            if (mode == 0) {
                *reinterpret_cast<float2*>(&C[(size_t)r0 * N + c]) = make_float2(v0, v1);
                *reinterpret_cast<float2*>(&C[(size_t)(r0 + 8) * N + c]) = make_float2(v2, v3);
            } else if (mode == 1) {
                __half h0,o0,h1,o1,h2,o2,h3,o3;
                split_hl(v0,h0,o0); split_hl(v1,h1,o1); split_hl(v2,h2,o2); split_hl(v3,h3,o3);
                *reinterpret_cast<__half2*>(&Ch[(size_t)r0*N + c]) = __half2(h0,h1);
                *reinterpret_cast<__half2*>(&Cl[(size_t)r0*N + c]) = __half2(o0,o1);
                *reinterpret_cast<__half2*>(&Ch[(size_t)(r0+8)*N + c]) = __half2(h2,h3);
                *reinterpret_cast<__half2*>(&Cl[(size_t)(r0+8)*N + c]) = __half2(o2,o3);
            } else {
                *reinterpret_cast<__half2*>(&V16[(size_t)r0*N + c]) = __floats2half2_rn(v0, v1);
                *reinterpret_cast<__half2*>(&V16[(size_t)(r0+8)*N + c]) = __floats2half2_rn(v2, v3);
            }
        }
}

// ---------------- weight convert: fp32 -> fp16 (scaled) ----------------
__global__ __launch_bounds__(256)
void conv_kernel(const float* __restrict__ src, __half* __restrict__ dst, int n4, float sc)
{
    int i = blockIdx.x * blockDim.x + threadIdx.x;
    if (i >= n4) return;
    float4 v = reinterpret_cast<const float4*>(src)[i];
    reinterpret_cast<__half2*>(dst)[i*2]   = __floats2half2_rn(v.x * sc, v.y * sc);
    reinterpret_cast<__half2*>(dst)[i*2+1] = __floats2half2_rn(v.z * sc, v.w * sc);
}

// ---------------- LayerNorm (+ modulation), writes fp16 hi/lo ----------------
__global__ __launch_bounds__(256)
void ln_kernel(const float* __restrict__ x, const float* __restrict__ latents,
               const float* __restrict__ shift, const float* __restrict__ scale,
               const float* __restrict__ ln1w, const float* __restrict__ ln1b,
               const float* __restrict__ ln2w, const float* __restrict__ ln2b)
{
    const int row = blockIdx.x, batch = row / L_, local = row % L_;
    const bool is_lat = (local >= N1_);
    const float* src = is_lat
        ? latents + ((size_t)batch * N2_ + (local - N1_)) * D_
        : x + ((size_t)batch * N1_ + local) * D_;

    const int t = threadIdx.x;
    float4 v = reinterpret_cast<const float4*>(src)[t];
    float s = v.x + v.y + v.z + v.w;
    float sq = v.x*v.x + v.y*v.y + v.z*v.z + v.w*v.w;

    __shared__ float red[16], red2[16];
    for (int o = 16; o > 0; o >>= 1) {
        s  += __shfl_down_sync(0xffffffff, s, o);
        sq += __shfl_down_sync(0xffffffff, sq, o);
    }
    int warp = t >> 5, lane = t & 31;
    if (lane == 0) { red[warp] = s; red2[warp] = sq; }
    __syncthreads();
    if (warp == 0) {
        s = (lane < 8) ? red[lane] : 0.f;
        sq = (lane < 8) ? red2[lane] : 0.f;
        for (int o = 4; o > 0; o >>= 1) {
            s  += __shfl_down_sync(0xffffffff, s, o);
            sq += __shfl_down_sync(0xffffffff, sq, o);
        }
        if (lane == 0) { red[0] = s; red2[0] = sq; }
    }
    __syncthreads();
    const float mu = red[0] * (1.0f / D_);
    const float var = red2[0] * (1.0f / D_) - mu * mu;
    const float rstd = rsqrtf(var + EPS_);

    float4 w4, b4, out;
    if (is_lat) {
        w4 = reinterpret_cast<const float4*>(ln2w)[t];
        b4 = reinterpret_cast<const float4*>(ln2b)[t];
    } else {
        w4 = reinterpret_cast<const float4*>(ln1w)[t];
        b4 = reinterpret_cast<const float4*>(ln1b)[t];
    }
    out.x = (v.x - mu) * rstd * w4.x + b4.x;
    out.y = (v.y - mu) * rstd * w4.y + b4.y;
    out.z = (v.z - mu) * rstd * w4.z + b4.z;
    out.w = (v.w - mu) * rstd * w4.w + b4.w;

    if (is_lat) {
        const float4 sc = reinterpret_cast<const float4*>(scale + (size_t)batch * D_)[t];
        const float4 sh = reinterpret_cast<const float4*>(shift + (size_t)batch * D_)[t];
        out.x = out.x * (1.0f + sc.x) + sh.x;
        out.y = out.y * (1.0f + sc.y) + sh.y;
        out.z = out.z * (1.0f + sc.z) + sh.z;
        out.w = out.w * (1.0f + sc.w) + sh.w;
    }

    __half h0,l0,h1,l1,h2,l2,h3,l3;
    split_hl(out.x,h0,l0); split_hl(out.y,h1,l1); split_hl(out.z,h2,l2); split_hl(out.w,h3,l3);
    __half2 hA(h0,h1), hB(h2,h3), lA(l0,l1), lB(l2,l3);
    {
        __half2* hp = reinterpret_cast<__half2*>(g_kvin_hi + (size_t)row * D_);
        __half2* lp = reinterpret_cast<__half2*>(g_kvin_lo + (size_t)row * D_);
        hp[t*2] = hA; hp[t*2+1] = hB; lp[t*2] = lA; lp[t*2+1] = lB;
    }
    if (is_lat) {
        const size_t lr = (size_t)batch * N2_ + (local - N1_);
        __half2* hp = reinterpret_cast<__half2*>(g_latm_hi + lr * D_);
        __half2* lp = reinterpret_cast<__half2*>(g_latm_lo + lr * D_);
        hp[t*2] = hA; hp[t*2+1] = hB; lp[t*2] = lA; lp[t*2+1] = lB;
    }
}

// ============================ mma.sync flash attention ============================
#define AT_ROWB 144
#define AQ_L 18432
#define AK_BASE 36864
#define AK_STAGE 27648
#define AKL 9216
#define AV 18432
#define A_SMEM 92160

__global__ __launch_bounds__(256, 1)
void attn_mma(const __half* __restrict__ qh, const __half* __restrict__ ql,
              const __half* __restrict__ kh, const __half* __restrict__ kl,
              const __half* __restrict__ v16,
              __half* __restrict__ oh, __half* __restrict__ ol)
{
    extern __shared__ char sm[];
    const uint32_t smb = smem_u32(sm);
    const int tid = threadIdx.x, wid = tid >> 5, lane = tid & 31;
    const int batch = blockIdx.x >> 4, head = blockIdx.x & 15;
    const int q0 = batch * N2_ + blockIdx.y * 128;
    const size_t kv0 = (size_t)batch * L_;

    for (int i = tid; i < 1024; i += 256) {
        const int row = i >> 3, ch = (i & 7) * 16;
        const size_t g = ((size_t)(q0 + row) * INNER_ + head * DH_) * 2;
        CP_ASYNC16(smb + row * AT_ROWB + ch, (const char*)qh + g + ch);
        CP_ASYNC16(smb + AQ_L + row * AT_ROWB + ch, (const char*)ql + g + ch);
    }
    CP_COMMIT();

    auto load_kv = [&](int t, int st) {
        const uint32_t sb = smb + AK_BASE + st * AK_STAGE;
        for (int i = tid; i < 512; i += 256) {
            const int row = i >> 3, ch = (i & 7) * 16;
            const size_t gr = kv0 + t * 64 + row;
            const size_t gk = (gr * INNER_ + head * DH_) * 2;
            CP_ASYNC16(sb + row * AT_ROWB + ch, (const char*)kh + gk + ch);
            CP_ASYNC16(sb + AKL + row * AT_ROWB + ch, (const char*)kl + gk + ch);
            CP_ASYNC16(sb + AV + row * AT_ROWB + ch, (const char*)v16 + gk + ch);
        }
        CP_COMMIT();
    };

    load_kv(0, 0);
    CP_WAIT(0);
    __syncthreads();

    uint32_t qfh[4][4], qfl[4][4];
    #pragma unroll
    for (int kk = 0; kk < 4; kk++) {
        const uint32_t ra = smb + (wid * 16 + (lane & 15)) * AT_ROWB + ((lane >> 4) << 4) + kk * 32;
        LDSM_X4(qfh[kk], ra);
        LDSM_X4(qfl[kk], ra + AQ_L);
    }

    float accO[8][4];
    #pragma unroll
    for (int nt = 0; nt < 8; nt++)
        #pragma unroll
        for (int c = 0; c < 4; c++) accO[nt][c] = 0.f;
    float m0 = -1e30f, m1 = -1e30f, l0 = 0.f, l1 = 0.f;

    const int NT = L_ / 64;
    for (int t = 0; t < NT; t++) {
        const int st = t & 1;
        if (t > 0) { CP_WAIT(0); __syncthreads(); }
        if (t + 1 < NT) load_kv(t + 1, st ^ 1);
        const uint32_t sb = smb + AK_BASE + st * AK_STAGE;

        float sacc[8][4];
        #pragma unroll
        for (int nt = 0; nt < 8; nt++)
            #pragma unroll
            for (int c = 0; c < 4; c++) sacc[nt][c] = 0.f;

        #pragma unroll
        for (int kk = 0; kk < 4; kk++) {
            uint32_t kbh[4][4], kbl[4][4];
            #pragma unroll
            for (int g = 0; g < 4; g++) {
                const uint32_t rb = sb + (g * 16 + ((lane >> 4) << 3) + (lane & 7)) * AT_ROWB
                                    + (((lane >> 3) & 1) << 4) + kk * 32;
                LDSM_X4(kbh[g], rb);
                LDSM_X4(kbl[g], rb + AKL);
            }
            #pragma unroll
            for (int g = 0; g < 4; g++) {
                MMAF16(sacc[2*g],   qfh[kk], kbh[g][0], kbh[g][1]);
                MMAF16(sacc[2*g+1], qfh[kk], kbh[g][2], kbh[g][3]);
            }
            #pragma unroll
            for (int g = 0; g < 4; g++) {
                MMAF16(sacc[2*g],   qfh[kk], kbl[g][0], kbl[g][1]);
                MMAF16(sacc[2*g+1], qfh[kk], kbl[g][2], kbl[g][3]);
            }
            #pragma unroll
            for (int g = 0; g < 4; g++) {
                MMAF16(sacc[2*g],   qfl[kk], kbh[g][0], kbh[g][1]);
                MMAF16(sacc[2*g+1], qfl[kk], kbh[g][2], kbh[g][3]);
            }
        }

        float tm0 = sacc[0][0], tm1 = sacc[0][2];
        #pragma unroll
        for (int nt = 0; nt < 8; nt++) {
            tm0 = fmaxf(tm0, fmaxf(sacc[nt][0], sacc[nt][1]));
            tm1 = fmaxf(tm1, fmaxf(sacc[nt][2], sacc[nt][3]));
        }
        tm0 = fmaxf(tm0, __shfl_xor_sync(0xffffffff, tm0, 1));
        tm0 = fmaxf(tm0, __shfl_xor_sync(0xffffffff, tm0, 2));
        tm1 = fmaxf(tm1, __shfl_xor_sync(0xffffffff, tm1, 1));
        tm1 = fmaxf(tm1, __shfl_xor_sync(0xffffffff, tm1, 2));

        const float mn0 = fmaxf(m0, tm0), mn1 = fmaxf(m1, tm1);
        const float c0 = exp2f(m0 - mn0), c1 = exp2f(m1 - mn1);
        m0 = mn0; m1 = mn1;

        float ls0 = 0.f, ls1 = 0.f;
        uint32_t pa[4][4];
        #pragma unroll
        for (int nt = 0; nt < 8; nt++) {
            const float p0 = exp2f(sacc[nt][0] - mn0);
            const float p1 = exp2f(sacc[nt][1] - mn0);
            const float p2 = exp2f(sacc[nt][2] - mn1);
            const float p3 = exp2f(sacc[nt][3] - mn1);
            ls0 += p0 + p1; ls1 += p2 + p3;
            __half2 ha = __floats2half2_rn(p0, p1);
            __half2 hb = __floats2half2_rn(p2, p3);
            pa[nt >> 1][(nt & 1) * 2 + 0] = *reinterpret_cast<uint32_t*>(&ha);
            pa[nt >> 1][(nt & 1) * 2 + 1] = *reinterpret_cast<uint32_t*>(&hb);
        }
        l0 = l0 * c0 + ls0;
        l1 = l1 * c1 + ls1;
        #pragma unroll
        for (int nt = 0; nt < 8; nt++) {
            accO[nt][0] *= c0; accO[nt][1] *= c0;
            accO[nt][2] *= c1; accO[nt][3] *= c1;
        }

        #pragma unroll
        for (int kt = 0; kt < 4; kt++) {
            uint32_t vb[4][4];
            #pragma unroll
            for (int g = 0; g < 4; g++) {
                const uint32_t rv = sb + AV + (kt * 16 + (lane & 15)) * AT_ROWB
                                    + g * 32 + ((lane >> 4) << 4);
                LDSM_X4_T(vb[g], rv);
            }
            #pragma unroll
            for (int g = 0; g < 4; g++) {
                MMAF16(accO[2*g],   pa[kt], vb[g][0], vb[g][1]);
                MMAF16(accO[2*g+1], pa[kt], vb[g][2], vb[g][3]);
            }
        }
    }

    l0 += __shfl_xor_sync(0xffffffff, l0, 1);
    l0 += __shfl_xor_sync(0xffffffff, l0, 2);
    l1 += __shfl_xor_sync(0xffffffff, l1, 1);
    l1 += __shfl_xor_sync(0xffffffff, l1, 2);
    const float i0 = 1.0f / l0, i1 = 1.0f / l1;

    const int qrow = q0 + wid * 16 + (lane >> 2);
    #pragma unroll
    for (int nt = 0; nt < 8; nt++) {
        const int col = head * DH_ + nt * 8 + (lane & 3) * 2;
        __half h0,lo0,h1,lo1,h2,lo2,h3,lo3;
        split_hl(accO[nt][0]*i0,h0,lo0); split_hl(accO[nt][1]*i0,h1,lo1);
        split_hl(accO[nt][2]*i1,h2,lo2); split_hl(accO[nt][3]*i1,h3,lo3);
        *reinterpret_cast<__half2*>(oh + (size_t)qrow*INNER_ + col) = __half2(h0,h1);
        *reinterpret_cast<__half2*>(ol + (size_t)qrow*INNER_ + col) = __half2(lo0,lo1);
        *reinterpret_cast<__half2*>(oh + (size_t)(qrow+8)*INNER_ + col) = __half2(h2,h3);
        *reinterpret_cast<__half2*>(ol + (size_t)(qrow+8)*INNER_ + col) = __half2(lo2,lo3);
    }
}

// ---------------- launch ----------------
extern "C" void kernel_launch(void* const* d_in, const int* in_sizes, int n_in,
                              void* d_out, int out_size)
{
    const float* x       = (const float*)d_in[0];
    const float* latents = (const float*)d_in[1];
    const float* shift   = (const float*)d_in[2];
    const float* scale   = (const float*)d_in[3];
    const float* ln1w    = (const float*)d_in[4];
    const float* ln1b    = (const float*)d_in[5];
    const float* ln2w    = (const float*)d_in[6];
    const float* ln2b    = (const float*)d_in[7];
    const float* Wq      = (const float*)d_in[8];
    const float* Wkv     = (const float*)d_in[9];
    const float* Wo      = (const float*)d_in[10];
    float* out = (float*)d_out;

    __half *kvin_h,*kvin_l,*latm_h,*latm_l,*wq16,*wkv16,*wo16;
    __half *att_h,*att_l,*q_h,*q_l,*k_h,*k_l,*v16;
    cudaGetSymbolAddress((void**)&kvin_h, g_kvin_hi);
    cudaGetSymbolAddress((void**)&kvin_l, g_kvin_lo);
    cudaGetSymbolAddress((void**)&latm_h, g_latm_hi);
    cudaGetSymbolAddress((void**)&latm_l, g_latm_lo);
    cudaGetSymbolAddress((void**)&wq16, g_wq16);
    cudaGetSymbolAddress((void**)&wkv16, g_wkv16);
    cudaGetSymbolAddress((void**)&wo16, g_wo16);
    cudaGetSymbolAddress((void**)&att_h, g_att_hi);
    cudaGetSymbolAddress((void**)&att_l, g_att_lo);
    cudaGetSymbolAddress((void**)&q_h, g_q_hi);
    cudaGetSymbolAddress((void**)&q_l, g_q_lo);
    cudaGetSymbolAddress((void**)&k_h, g_k_hi);
    cudaGetSymbolAddress((void**)&k_l, g_k_lo);
    cudaGetSymbolAddress((void**)&v16, g_v16);

    cudaFuncSetAttribute(gemm_f16<2>, cudaFuncAttributeMaxDynamicSharedMemorySize, 3 * GS_STAGE);
    cudaFuncSetAttribute(gemm_f16<1>, cudaFuncAttributeMaxDynamicSharedMemorySize, 3 * GS_STAGE);
    cudaFuncSetAttribute(attn_mma, cudaFuncAttributeMaxDynamicSharedMemorySize, A_SMEM);

    const float qsc = 0.125f * 1.44269504088896340736f;  // attn_scale^2 * log2(e)
    conv_kernel<<<INNER_ * D_ / 1024, 256>>>(Wq, wq16, INNER_ * D_ / 4, qsc);
    conv_kernel<<<2 * INNER_ * D_ / 1024, 256>>>(Wkv, wkv16, 2 * INNER_ * D_ / 4, 1.0f);
    conv_kernel<<<D_ * INNER_ / 1024, 256>>>(Wo, wo16, D_ * INNER_ / 4, 1.0f);

    ln_kernel<<<B_ * L_, 256>>>(x, latents, shift, scale, ln1w, ln1b, ln2w, ln2b);

    { // q (fp16 hi/lo out), 2-pass
        dim3 grid(INNER_ / 128, (B_ * N2_) / 128);
        gemm_f16<2><<<grid, 256, 3 * GS_STAGE>>>(latm_h, latm_l, wq16,
                                                 nullptr, q_h, q_l, nullptr, INNER_, D_, 1);
    }
    { // K (fp16 hi/lo out), 2-pass
        dim3 grid(INNER_ / 128, (B_ * L_) / 128);
        gemm_f16<2><<<grid, 256, 3 * GS_STAGE>>>(kvin_h, kvin_l, wkv16,
                                                 nullptr, k_h, k_l, nullptr, INNER_, D_, 1);
    }
    { // V (fp16 single out), 1-pass
        dim3 grid(INNER_ / 128, (B_ * L_) / 128);
        gemm_f16<1><<<grid, 256, 3 * GS_STAGE>>>(kvin_h, nullptr, wkv16 + (size_t)INNER_ * D_,
                                                 nullptr, nullptr, nullptr, v16, INNER_, D_, 3);
    }
    { // attention
        dim3 grid(B_ * HEADS_, N2_ / 128);
        attn_mma<<<grid, 256, A_SMEM>>>(q_h, q_l, k_h, k_l, v16, att_h, att_l);
    }
    { // out (fp32), 2-pass
        dim3 grid(D_ / 128, (B_ * N2_) / 128);
        gemm_f16<2><<<grid, 256, 3 * GS_STAGE>>>(att_h, att_l, wo16,
                                                 out, nullptr, nullptr, nullptr, D_, INNER_, 0);
    }
    (void)in_sizes; (void)n_in; (void)out_size;
}

// round 8
// speedup vs baseline: 5.2541x; 1.3281x over previous
#include <cuda_runtime.h>
#include <cuda_fp16.h>
#include <math.h>
#include <stdint.h>

#define B_   8
#define N1_  4096
#define N2_  256
#define D_   1024
#define INNER_ 1024
#define HEADS_ 16
#define DH_  64
#define L_   (N1_ + N2_)
#define EPS_ 1e-5f

__device__ __half g_kvin16[(size_t)B_ * L_ * D_];
__device__ __half g_latm16[(size_t)B_ * N2_ * D_];
__device__ __half g_wq16 [(size_t)INNER_ * D_];
__device__ __half g_wkv16[(size_t)2 * INNER_ * D_];
__device__ __half g_wo16 [(size_t)D_ * INNER_];
__device__ __half g_att_hi[(size_t)B_ * N2_ * INNER_];
__device__ __half g_att_lo[(size_t)B_ * N2_ * INNER_];
__device__ __half g_q16[(size_t)B_ * N2_ * INNER_];
__device__ __half g_k16[(size_t)B_ * L_ * INNER_];
__device__ __half g_v16[(size_t)B_ * L_ * INNER_];

__device__ __forceinline__ uint32_t smem_u32(const void* p) {
    uint32_t a;
    asm("{ .reg .u64 t; cvta.to.shared.u64 t, %1; cvt.u32.u64 %0, t; }" : "=r"(a) : "l"(p));
    return a;
}
#define CP_ASYNC16(dst, src) \
    asm volatile("cp.async.cg.shared.global [%0], [%1], 16;" :: "r"(dst), "l"(src))
#define CP_COMMIT() asm volatile("cp.async.commit_group;" ::: "memory")
#define CP_WAIT(n)  asm volatile("cp.async.wait_group %0;" :: "n"(n) : "memory")
#define LDSM_X4(r, addr) \
    asm volatile("ldmatrix.sync.aligned.m8n8.x4.shared.b16 {%0,%1,%2,%3}, [%4];" \
                 : "=r"((r)[0]), "=r"((r)[1]), "=r"((r)[2]), "=r"((r)[3]) : "r"(addr))
#define LDSM_X4_T(r, addr) \
    asm volatile("ldmatrix.sync.aligned.m8n8.x4.trans.shared.b16 {%0,%1,%2,%3}, [%4];" \
                 : "=r"((r)[0]), "=r"((r)[1]), "=r"((r)[2]), "=r"((r)[3]) : "r"(addr))
#define MMAF16(acc, a, b0, b1) \
    asm volatile("mma.sync.aligned.m16n8k16.row.col.f32.f16.f16.f32 " \
        "{%0,%1,%2,%3}, {%4,%5,%6,%7}, {%8,%9}, {%0,%1,%2,%3};" \
        : "+f"((acc)[0]), "+f"((acc)[1]), "+f"((acc)[2]), "+f"((acc)[3]) \
        : "r"((a)[0]), "r"((a)[1]), "r"((a)[2]), "r"((a)[3]), "r"(b0), "r"(b1))

__device__ __forceinline__ void split_hl(float v, __half& h, __half& l) {
    h = __float2half_rn(v);
    l = __float2half_rn(v - __half2float(h));
}

// ============================ fp16 mma.sync GEMM (NPASS=1|2) ============================
// C[M,N] = (Ah[+Al])[M,K] * B16[N,K]^T, fp32 acc. 128x128 tile, BK=32, 3-stage cp.async.
// mode 0: fp32 C (stride N). mode 2: c<INNER -> K16, else V16 (both stride INNER).
// mode 3: single fp16 to V16 (stride N).
#define GS_ARR   10240
#define GS_STAGE 30720
#define GS_ROWB  80

template<int NPASS>
__global__ __launch_bounds__(256, 1)
void gemm_f16(const __half* __restrict__ Ah, const __half* __restrict__ Al,
              const __half* __restrict__ Bh,
              float* __restrict__ C,
              __half* __restrict__ K16, __half* __restrict__ V16,
              int N, int K, int mode)
{
    extern __shared__ char smraw[];
    const uint32_t smbase = smem_u32(smraw);
    const int tid = threadIdx.x, wid = tid >> 5, lane = tid & 31;
    const int bm = blockIdx.y * 128, bn = blockIdx.x * 128;
    const int wm = (wid & 3) * 32, wn = (wid >> 2) * 64;

    const char* srcs[3] = { (const char*)Ah, (const char*)Al, (const char*)Bh };
    auto load_stage = [&](int kt, int st) {
        #pragma unroll
        for (int arr = 0; arr < 3; arr++) {
            if (NPASS == 1 && arr == 1) continue;
            const int rb = (arr < 2) ? bm : bn;
            #pragma unroll
            for (int j = 0; j < 2; j++) {
                const int ch = tid * 2 + j;
                const int row = ch >> 2, col = ch & 3;
                const char* src = srcs[arr] + ((size_t)(rb + row) * K + kt * 32) * 2 + col * 16;
                CP_ASYNC16(smbase + st * GS_STAGE + arr * GS_ARR + row * GS_ROWB + col * 16, src);
            }
        }
        CP_COMMIT();
    };

    float acc[2][8][4];
    #pragma unroll
    for (int i = 0; i < 2; i++)
        #pragma unroll
        for (int t = 0; t < 8; t++)
            #pragma unroll
            for (int c = 0; c < 4; c++) acc[i][t][c] = 0.f;

    const int niter = K / 32;
    load_stage(0, 0);
    if (niter > 1) load_stage(1, 1);

    for (int kt = 0; kt < niter; kt++) {
        const int st = kt % 3;
        CP_WAIT(1);
        __syncthreads();
        if (kt + 2 < niter) load_stage(kt + 2, (kt + 2) % 3);

        const uint32_t base = smbase + st * GS_STAGE;
        #pragma unroll
        for (int kk = 0; kk < 2; kk++) {
            uint32_t ah[2][4], al[2][4], bb[4][4];
            #pragma unroll
            for (int i = 0; i < 2; i++) {
                const uint32_t ra = base + (uint32_t)((wm + i * 16 + (lane & 15)) * GS_ROWB
                                    + ((lane >> 4) << 4) + kk * 32);
                LDSM_X4(ah[i], ra);
                if (NPASS == 2) LDSM_X4(al[i], ra + GS_ARR);
            }
            #pragma unroll
            for (int g = 0; g < 4; g++) {
                const uint32_t rb = base + 2 * GS_ARR
                    + (uint32_t)((wn + g * 16 + ((lane >> 4) << 3) + (lane & 7)) * GS_ROWB
                                 + (((lane >> 3) & 1) << 4) + kk * 32);
                LDSM_X4(bb[g], rb);
            }
            #pragma unroll
            for (int i = 0; i < 2; i++)
                #pragma unroll
                for (int g = 0; g < 4; g++) {
                    MMAF16(acc[i][2*g],   ah[i], bb[g][0], bb[g][1]);
                    MMAF16(acc[i][2*g+1], ah[i], bb[g][2], bb[g][3]);
                }
            if (NPASS == 2) {
                #pragma unroll
                for (int i = 0; i < 2; i++)
                    #pragma unroll
                    for (int g = 0; g < 4; g++) {
                        MMAF16(acc[i][2*g],   al[i], bb[g][0], bb[g][1]);
                        MMAF16(acc[i][2*g+1], al[i], bb[g][2], bb[g][3]);
                    }
            }
        }
        __syncthreads();
    }

    #pragma unroll
    for (int i = 0; i < 2; i++)
        #pragma unroll
        for (int t = 0; t < 8; t++) {
            const int r0 = bm + wm + i * 16 + (lane >> 2);
            const int c  = bn + wn + t * 8 + (lane & 3) * 2;
            const float v0 = acc[i][t][0], v1 = acc[i][t][1];
            const float v2 = acc[i][t][2], v3 = acc[i][t][3];
            if (mode == 0) {
                *reinterpret_cast<float2*>(&C[(size_t)r0 * N + c]) = make_float2(v0, v1);
                *reinterpret_cast<float2*>(&C[(size_t)(r0 + 8) * N + c]) = make_float2(v2, v3);
            } else if (mode == 2) {
                __half* dst = (c < INNER_) ? K16 : V16;
                const int cc = (c < INNER_) ? c : c - INNER_;
                *reinterpret_cast<__half2*>(&dst[(size_t)r0*INNER_ + cc]) = __floats2half2_rn(v0, v1);
                *reinterpret_cast<__half2*>(&dst[(size_t)(r0+8)*INNER_ + cc]) = __floats2half2_rn(v2, v3);
            } else {
                *reinterpret_cast<__half2*>(&V16[(size_t)r0*N + c]) = __floats2half2_rn(v0, v1);
                *reinterpret_cast<__half2*>(&V16[(size_t)(r0+8)*N + c]) = __floats2half2_rn(v2, v3);
            }
        }
}

// ---------------- weight convert: fp32 -> fp16 (scaled) ----------------
__global__ __launch_bounds__(256)
void conv_kernel(const float* __restrict__ src, __half* __restrict__ dst, int n4, float sc)
{
    int i = blockIdx.x * blockDim.x + threadIdx.x;
    if (i >= n4) return;
    float4 v = reinterpret_cast<const float4*>(src)[i];
    reinterpret_cast<__half2*>(dst)[i*2]   = __floats2half2_rn(v.x * sc, v.y * sc);
    reinterpret_cast<__half2*>(dst)[i*2+1] = __floats2half2_rn(v.z * sc, v.w * sc);
}

// ---------------- LayerNorm (+ modulation), writes single fp16 ----------------
__global__ __launch_bounds__(256)
void ln_kernel(const float* __restrict__ x, const float* __restrict__ latents,
               const float* __restrict__ shift, const float* __restrict__ scale,
               const float* __restrict__ ln1w, const float* __restrict__ ln1b,
               const float* __restrict__ ln2w, const float* __restrict__ ln2b)
{
    const int row = blockIdx.x, batch = row / L_, local = row % L_;
    const bool is_lat = (local >= N1_);
    const float* src = is_lat
        ? latents + ((size_t)batch * N2_ + (local - N1_)) * D_
        : x + ((size_t)batch * N1_ + local) * D_;

    const int t = threadIdx.x;
    float4 v = reinterpret_cast<const float4*>(src)[t];
    float s = v.x + v.y + v.z + v.w;
    float sq = v.x*v.x + v.y*v.y + v.z*v.z + v.w*v.w;

    __shared__ float red[16], red2[16];
    for (int o = 16; o > 0; o >>= 1) {
        s  += __shfl_down_sync(0xffffffff, s, o);
        sq += __shfl_down_sync(0xffffffff, sq, o);
    }
    int warp = t >> 5, lane = t & 31;
    if (lane == 0) { red[warp] = s; red2[warp] = sq; }
    __syncthreads();
    if (warp == 0) {
        s = (lane < 8) ? red[lane] : 0.f;
        sq = (lane < 8) ? red2[lane] : 0.f;
        for (int o = 4; o > 0; o >>= 1) {
            s  += __shfl_down_sync(0xffffffff, s, o);
            sq += __shfl_down_sync(0xffffffff, sq, o);
        }
        if (lane == 0) { red[0] = s; red2[0] = sq; }
    }
    __syncthreads();
    const float mu = red[0] * (1.0f / D_);
    const float var = red2[0] * (1.0f / D_) - mu * mu;
    const float rstd = rsqrtf(var + EPS_);

    float4 w4, b4, out;
    if (is_lat) {
        w4 = reinterpret_cast<const float4*>(ln2w)[t];
        b4 = reinterpret_cast<const float4*>(ln2b)[t];
    } else {
        w4 = reinterpret_cast<const float4*>(ln1w)[t];
        b4 = reinterpret_cast<const float4*>(ln1b)[t];
    }
    out.x = (v.x - mu) * rstd * w4.x + b4.x;
    out.y = (v.y - mu) * rstd * w4.y + b4.y;
    out.z = (v.z - mu) * rstd * w4.z + b4.z;
    out.w = (v.w - mu) * rstd * w4.w + b4.w;

    if (is_lat) {
        const float4 sc = reinterpret_cast<const float4*>(scale + (size_t)batch * D_)[t];
        const float4 sh = reinterpret_cast<const float4*>(shift + (size_t)batch * D_)[t];
        out.x = out.x * (1.0f + sc.x) + sh.x;
        out.y = out.y * (1.0f + sc.y) + sh.y;
        out.z = out.z * (1.0f + sc.z) + sh.z;
        out.w = out.w * (1.0f + sc.w) + sh.w;
    }

    __half2 hA = __floats2half2_rn(out.x, out.y);
    __half2 hB = __floats2half2_rn(out.z, out.w);
    {
        __half2* hp = reinterpret_cast<__half2*>(g_kvin16 + (size_t)row * D_);
        hp[t*2] = hA; hp[t*2+1] = hB;
    }
    if (is_lat) {
        const size_t lr = (size_t)batch * N2_ + (local - N1_);
        __half2* hp = reinterpret_cast<__half2*>(g_latm16 + lr * D_);
        hp[t*2] = hA; hp[t*2+1] = hB;
    }
}

// ============================ mma.sync flash attention (fp16 QK, 1 pass) ============================
#define AT_ROWB 144
#define AK_BASE 18432
#define AK_STAGE 18432
#define AV 9216
#define A_SMEM 55296

__global__ __launch_bounds__(256, 1)
void attn_mma(const __half* __restrict__ q16, const __half* __restrict__ k16,
              const __half* __restrict__ v16,
              __half* __restrict__ oh, __half* __restrict__ ol)
{
    extern __shared__ char sm[];
    const uint32_t smb = smem_u32(sm);
    const int tid = threadIdx.x, wid = tid >> 5, lane = tid & 31;
    const int batch = blockIdx.x >> 4, head = blockIdx.x & 15;
    const int q0 = batch * N2_ + blockIdx.y * 128;
    const size_t kv0 = (size_t)batch * L_;

    for (int i = tid; i < 1024; i += 256) {
        const int row = i >> 3, ch = (i & 7) * 16;
        const size_t g = ((size_t)(q0 + row) * INNER_ + head * DH_) * 2;
        CP_ASYNC16(smb + row * AT_ROWB + ch, (const char*)q16 + g + ch);
    }
    CP_COMMIT();

    auto load_kv = [&](int t, int st) {
        const uint32_t sb = smb + AK_BASE + st * AK_STAGE;
        for (int i = tid; i < 512; i += 256) {
            const int row = i >> 3, ch = (i & 7) * 16;
            const size_t gr = kv0 + t * 64 + row;
            const size_t gk = (gr * INNER_ + head * DH_) * 2;
            CP_ASYNC16(sb + row * AT_ROWB + ch, (const char*)k16 + gk + ch);
            CP_ASYNC16(sb + AV + row * AT_ROWB + ch, (const char*)v16 + gk + ch);
        }
        CP_COMMIT();
    };

    load_kv(0, 0);
    CP_WAIT(0);
    __syncthreads();

    uint32_t qf[4][4];
    #pragma unroll
    for (int kk = 0; kk < 4; kk++) {
        const uint32_t ra = smb + (wid * 16 + (lane & 15)) * AT_ROWB + ((lane >> 4) << 4) + kk * 32;
        LDSM_X4(qf[kk], ra);
    }

    float accO[8][4];
    #pragma unroll
    for (int nt = 0; nt < 8; nt++)
        #pragma unroll
        for (int c = 0; c < 4; c++) accO[nt][c] = 0.f;
    float m0 = -1e30f, m1 = -1e30f, l0 = 0.f, l1 = 0.f;

    const int NT = L_ / 64;
    for (int t = 0; t < NT; t++) {
        const int st = t & 1;
        if (t > 0) { CP_WAIT(0); __syncthreads(); }
        if (t + 1 < NT) load_kv(t + 1, st ^ 1);
        const uint32_t sb = smb + AK_BASE + st * AK_STAGE;

        float sacc[8][4];
        #pragma unroll
        for (int nt = 0; nt < 8; nt++)
            #pragma unroll
            for (int c = 0; c < 4; c++) sacc[nt][c] = 0.f;

        #pragma unroll
        for (int kk = 0; kk < 4; kk++) {
            uint32_t kb[4][4];
            #pragma unroll
            for (int g = 0; g < 4; g++) {
                const uint32_t rb = sb + (g * 16 + ((lane >> 4) << 3) + (lane & 7)) * AT_ROWB
                                    + (((lane >> 3) & 1) << 4) + kk * 32;
                LDSM_X4(kb[g], rb);
            }
            #pragma unroll
            for (int g = 0; g < 4; g++) {
                MMAF16(sacc[2*g],   qf[kk], kb[g][0], kb[g][1]);
                MMAF16(sacc[2*g+1], qf[kk], kb[g][2], kb[g][3]);
            }
        }

        float tm0 = sacc[0][0], tm1 = sacc[0][2];
        #pragma unroll
        for (int nt = 0; nt < 8; nt++) {
            tm0 = fmaxf(tm0, fmaxf(sacc[nt][0], sacc[nt][1]));
            tm1 = fmaxf(tm1, fmaxf(sacc[nt][2], sacc[nt][3]));
        }
        tm0 = fmaxf(tm0, __shfl_xor_sync(0xffffffff, tm0, 1));
        tm0 = fmaxf(tm0, __shfl_xor_sync(0xffffffff, tm0, 2));
        tm1 = fmaxf(tm1, __shfl_xor_sync(0xffffffff, tm1, 1));
        tm1 = fmaxf(tm1, __shfl_xor_sync(0xffffffff, tm1, 2));

        const float mn0 = fmaxf(m0, tm0), mn1 = fmaxf(m1, tm1);
        const float c0 = exp2f(m0 - mn0), c1 = exp2f(m1 - mn1);
        m0 = mn0; m1 = mn1;

        float ls0 = 0.f, ls1 = 0.f;
        uint32_t pa[4][4];
        #pragma unroll
        for (int nt = 0; nt < 8; nt++) {
            const float p0 = exp2f(sacc[nt][0] - mn0);
            const float p1 = exp2f(sacc[nt][1] - mn0);
            const float p2 = exp2f(sacc[nt][2] - mn1);
            const float p3 = exp2f(sacc[nt][3] - mn1);
            ls0 += p0 + p1; ls1 += p2 + p3;
            __half2 ha = __floats2half2_rn(p0, p1);
            __half2 hb = __floats2half2_rn(p2, p3);
            pa[nt >> 1][(nt & 1) * 2 + 0] = *reinterpret_cast<uint32_t*>(&ha);
            pa[nt >> 1][(nt & 1) * 2 + 1] = *reinterpret_cast<uint32_t*>(&hb);
        }
        l0 = l0 * c0 + ls0;
        l1 = l1 * c1 + ls1;
        #pragma unroll
        for (int nt = 0; nt < 8; nt++) {
            accO[nt][0] *= c0; accO[nt][1] *= c0;
            accO[nt][2] *= c1; accO[nt][3] *= c1;
        }

        #pragma unroll
        for (int kt = 0; kt < 4; kt++) {
            uint32_t vb[4][4];
            #pragma unroll
            for (int g = 0; g < 4; g++) {
                const uint32_t rv = sb + AV + (kt * 16 + (lane & 15)) * AT_ROWB
                                    + g * 32 + ((lane >> 4) << 4);
                LDSM_X4_T(vb[g], rv);
            }
            #pragma unroll
            for (int g = 0; g < 4; g++) {
                MMAF16(accO[2*g],   pa[kt], vb[g][0], vb[g][1]);
                MMAF16(accO[2*g+1], pa[kt], vb[g][2], vb[g][3]);
            }
        }
    }

    l0 += __shfl_xor_sync(0xffffffff, l0, 1);
    l0 += __shfl_xor_sync(0xffffffff, l0, 2);
    l1 += __shfl_xor_sync(0xffffffff, l1, 1);
    l1 += __shfl_xor_sync(0xffffffff, l1, 2);
    const float i0 = 1.0f / l0, i1 = 1.0f / l1;

    const int qrow = q0 + wid * 16 + (lane >> 2);
    #pragma unroll
    for (int nt = 0; nt < 8; nt++) {
        const int col = head * DH_ + nt * 8 + (lane & 3) * 2;
        __half h0,lo0,h1,lo1,h2,lo2,h3,lo3;
        split_hl(accO[nt][0]*i0,h0,lo0); split_hl(accO[nt][1]*i0,h1,lo1);
        split_hl(accO[nt][2]*i1,h2,lo2); split_hl(accO[nt][3]*i1,h3,lo3);
        *reinterpret_cast<__half2*>(oh + (size_t)qrow*INNER_ + col) = __half2(h0,h1);
        *reinterpret_cast<__half2*>(ol + (size_t)qrow*INNER_ + col) = __half2(lo0,lo1);
        *reinterpret_cast<__half2*>(oh + (size_t)(qrow+8)*INNER_ + col) = __half2(h2,h3);
        *reinterpret_cast<__half2*>(ol + (size_t)(qrow+8)*INNER_ + col) = __half2(lo2,lo3);
    }
}

// ---------------- launch ----------------
extern "C" void kernel_launch(void* const* d_in, const int* in_sizes, int n_in,
                              void* d_out, int out_size)
{
    const float* x       = (const float*)d_in[0];
    const float* latents = (const float*)d_in[1];
    const float* shift   = (const float*)d_in[2];
    const float* scale   = (const float*)d_in[3];
    const float* ln1w    = (const float*)d_in[4];
    const float* ln1b    = (const float*)d_in[5];
    const float* ln2w    = (const float*)d_in[6];
    const float* ln2b    = (const float*)d_in[7];
    const float* Wq      = (const float*)d_in[8];
    const float* Wkv     = (const float*)d_in[9];
    const float* Wo      = (const float*)d_in[10];
    float* out = (float*)d_out;

    __half *kvin16,*latm16,*wq16,*wkv16,*wo16,*att_h,*att_l,*q16,*k16,*v16;
    cudaGetSymbolAddress((void**)&kvin16, g_kvin16);
    cudaGetSymbolAddress((void**)&latm16, g_latm16);
    cudaGetSymbolAddress((void**)&wq16, g_wq16);
    cudaGetSymbolAddress((void**)&wkv16, g_wkv16);
    cudaGetSymbolAddress((void**)&wo16, g_wo16);
    cudaGetSymbolAddress((void**)&att_h, g_att_hi);
    cudaGetSymbolAddress((void**)&att_l, g_att_lo);
    cudaGetSymbolAddress((void**)&q16, g_q16);
    cudaGetSymbolAddress((void**)&k16, g_k16);
    cudaGetSymbolAddress((void**)&v16, g_v16);

    cudaFuncSetAttribute(gemm_f16<2>, cudaFuncAttributeMaxDynamicSharedMemorySize, 3 * GS_STAGE);
    cudaFuncSetAttribute(gemm_f16<1>, cudaFuncAttributeMaxDynamicSharedMemorySize, 3 * GS_STAGE);
    cudaFuncSetAttribute(attn_mma, cudaFuncAttributeMaxDynamicSharedMemorySize, A_SMEM);

    const float qsc = 0.125f * 1.44269504088896340736f;  // attn_scale^2 * log2(e)
    conv_kernel<<<INNER_ * D_ / 1024, 256>>>(Wq, wq16, INNER_ * D_ / 4, qsc);
    conv_kernel<<<2 * INNER_ * D_ / 1024, 256>>>(Wkv, wkv16, 2 * INNER_ * D_ / 4, 1.0f);
    conv_kernel<<<D_ * INNER_ / 1024, 256>>>(Wo, wo16, D_ * INNER_ / 4, 1.0f);

    ln_kernel<<<B_ * L_, 256>>>(x, latents, shift, scale, ln1w, ln1b, ln2w, ln2b);

    { // q = latm @ (qsc*Wq)^T, 1-pass, fp16 out
        dim3 grid(INNER_ / 128, (B_ * N2_) / 128);
        gemm_f16<1><<<grid, 256, 3 * GS_STAGE>>>(latm16, nullptr, wq16,
                                                 nullptr, nullptr, q16, INNER_, D_, 3);
    }
    { // fused KV: 1-pass, K16 + V16 out
        dim3 grid((2 * INNER_) / 128, (B_ * L_) / 128);
        gemm_f16<1><<<grid, 256, 3 * GS_STAGE>>>(kvin16, nullptr, wkv16,
                                                 nullptr, k16, v16, 2 * INNER_, D_, 2);
    }
    { // attention (fp16 QK single pass)
        dim3 grid(B_ * HEADS_, N2_ / 128);
        attn_mma<<<grid, 256, A_SMEM>>>(q16, k16, v16, att_h, att_l);
    }
    { // out = att @ Wo^T, 2-pass (att hi/lo), fp32 out
        dim3 grid(D_ / 128, (B_ * N2_) / 128);
        gemm_f16<2><<<grid, 256, 3 * GS_STAGE>>>(att_h, att_l, wo16,
                                                 out, nullptr, nullptr, D_, INNER_, 0);
    }
    (void)in_sizes; (void)n_in; (void)out_size;
}

// round 9
// speedup vs baseline: 6.3358x; 1.2059x over previous
#include <cuda_runtime.h>
#include <cuda_fp16.h>
#include <math.h>
#include <stdint.h>

#define B_   8
#define N1_  4096
#define N2_  256
#define D_   1024
#define INNER_ 1024
#define HEADS_ 16
#define DH_  64
#define L_   (N1_ + N2_)
#define EPS_ 1e-5f

__device__ __half g_kvin16[(size_t)B_ * L_ * D_];
__device__ __half g_latm16[(size_t)B_ * N2_ * D_];
__device__ __half g_wq16 [(size_t)INNER_ * D_];
__device__ __half g_wkv16[(size_t)2 * INNER_ * D_];
__device__ __half g_wo16 [(size_t)D_ * INNER_];
__device__ __half g_att16[(size_t)B_ * N2_ * INNER_];
__device__ __half g_q16[(size_t)B_ * N2_ * INNER_];
__device__ __half g_k16[(size_t)B_ * L_ * INNER_];
__device__ __half g_v16[(size_t)B_ * L_ * INNER_];

__device__ __forceinline__ uint32_t smem_u32(const void* p) {
    uint32_t a;
    asm("{ .reg .u64 t; cvta.to.shared.u64 t, %1; cvt.u32.u64 %0, t; }" : "=r"(a) : "l"(p));
    return a;
}
#define CP_ASYNC16(dst, src) \
    asm volatile("cp.async.cg.shared.global [%0], [%1], 16;" :: "r"(dst), "l"(src))
#define CP_COMMIT() asm volatile("cp.async.commit_group;" ::: "memory")
#define CP_WAIT(n)  asm volatile("cp.async.wait_group %0;" :: "n"(n) : "memory")
#define LDSM_X4(r, addr) \
    asm volatile("ldmatrix.sync.aligned.m8n8.x4.shared.b16 {%0,%1,%2,%3}, [%4];" \
                 : "=r"((r)[0]), "=r"((r)[1]), "=r"((r)[2]), "=r"((r)[3]) : "r"(addr))
#define LDSM_X4_T(r, addr) \
    asm volatile("ldmatrix.sync.aligned.m8n8.x4.trans.shared.b16 {%0,%1,%2,%3}, [%4];" \
                 : "=r"((r)[0]), "=r"((r)[1]), "=r"((r)[2]), "=r"((r)[3]) : "r"(addr))
#define MMAF16(acc, a, b0, b1) \
    asm volatile("mma.sync.aligned.m16n8k16.row.col.f32.f16.f16.f32 " \
        "{%0,%1,%2,%3}, {%4,%5,%6,%7}, {%8,%9}, {%0,%1,%2,%3};" \
        : "+f"((acc)[0]), "+f"((acc)[1]), "+f"((acc)[2]), "+f"((acc)[3]) \
        : "r"((a)[0]), "r"((a)[1]), "r"((a)[2]), "r"((a)[3]), "r"(b0), "r"(b1))

// ============================ fp16 mma.sync GEMM ============================
// C[M,N] = A16[M,K] * B16[N,K]^T, fp32 acc. CTA tile 128x256, warp tile 64x64
// (8 warps as 2x4), BK=32, 3-stage cp.async.
// mode 0: fp32 C (stride N). mode 2: c<INNER -> K16 else V16 (stride INNER).
// mode 3: single fp16 to O16 (stride N).
#define GS_ROWB  80
#define GSA      10240
#define GS_STAGE 30720

__global__ __launch_bounds__(256, 1)
void gemm_f16(const __half* __restrict__ A16, const __half* __restrict__ B16,
              float* __restrict__ C,
              __half* __restrict__ K16, __half* __restrict__ V16,
              __half* __restrict__ O16,
              int N, int K, int mode)
{
    extern __shared__ char smraw[];
    const uint32_t smbase = smem_u32(smraw);
    const int tid = threadIdx.x, wid = tid >> 5, lane = tid & 31;
    const int bm = blockIdx.y * 128, bn = blockIdx.x * 256;
    const int wm = (wid & 1) * 64, wn = (wid >> 1) * 64;

    auto load_stage = [&](int kt, int st) {
        const uint32_t sb = smbase + st * GS_STAGE;
        #pragma unroll
        for (int it = 0; it < 6; it++) {
            const int c = tid + it * 256;      // 0..1535
            const bool isA = c < 512;
            const int cc = isA ? c : c - 512;
            const int row = cc >> 2, col = cc & 3;
            const char* src = (isA
                ? (const char*)A16 + ((size_t)(bm + row) * K + kt * 32) * 2
                : (const char*)B16 + ((size_t)(bn + row) * K + kt * 32) * 2) + col * 16;
            CP_ASYNC16(sb + (isA ? 0u : (uint32_t)GSA) + row * GS_ROWB + col * 16, src);
        }
        CP_COMMIT();
    };

    float acc[4][8][4];
    #pragma unroll
    for (int i = 0; i < 4; i++)
        #pragma unroll
        for (int t = 0; t < 8; t++)
            #pragma unroll
            for (int c = 0; c < 4; c++) acc[i][t][c] = 0.f;

    const int niter = K / 32;
    load_stage(0, 0);
    if (niter > 1) load_stage(1, 1);

    for (int kt = 0; kt < niter; kt++) {
        const int st = kt % 3;
        CP_WAIT(1);
        __syncthreads();
        if (kt + 2 < niter) load_stage(kt + 2, (kt + 2) % 3);

        const uint32_t base = smbase + st * GS_STAGE;
        #pragma unroll
        for (int kk = 0; kk < 2; kk++) {
            uint32_t af[4][4], bf[4][4];
            #pragma unroll
            for (int i = 0; i < 4; i++) {
                const uint32_t ra = base + (uint32_t)((wm + i * 16 + (lane & 15)) * GS_ROWB
                                    + ((lane >> 4) << 4) + kk * 32);
                LDSM_X4(af[i], ra);
            }
            #pragma unroll
            for (int g = 0; g < 4; g++) {
                const uint32_t rb = base + GSA
                    + (uint32_t)((wn + g * 16 + ((lane >> 4) << 3) + (lane & 7)) * GS_ROWB
                                 + (((lane >> 3) & 1) << 4) + kk * 32);
                LDSM_X4(bf[g], rb);
            }
            #pragma unroll
            for (int i = 0; i < 4; i++)
                #pragma unroll
                for (int g = 0; g < 4; g++) {
                    MMAF16(acc[i][2*g],   af[i], bf[g][0], bf[g][1]);
                    MMAF16(acc[i][2*g+1], af[i], bf[g][2], bf[g][3]);
                }
        }
        __syncthreads();
    }

    #pragma unroll
    for (int i = 0; i < 4; i++)
        #pragma unroll
        for (int t = 0; t < 8; t++) {
            const int r0 = bm + wm + i * 16 + (lane >> 2);
            const int c  = bn + wn + t * 8 + (lane & 3) * 2;
            const float v0 = acc[i][t][0], v1 = acc[i][t][1];
            const float v2 = acc[i][t][2], v3 = acc[i][t][3];
            if (mode == 0) {
                *reinterpret_cast<float2*>(&C[(size_t)r0 * N + c]) = make_float2(v0, v1);
                *reinterpret_cast<float2*>(&C[(size_t)(r0 + 8) * N + c]) = make_float2(v2, v3);
            } else if (mode == 2) {
                __half* dst = (c < INNER_) ? K16 : V16;
                const int cc = (c < INNER_) ? c : c - INNER_;
                *reinterpret_cast<__half2*>(&dst[(size_t)r0*INNER_ + cc]) = __floats2half2_rn(v0, v1);
                *reinterpret_cast<__half2*>(&dst[(size_t)(r0+8)*INNER_ + cc]) = __floats2half2_rn(v2, v3);
            } else {
                *reinterpret_cast<__half2*>(&O16[(size_t)r0*N + c]) = __floats2half2_rn(v0, v1);
                *reinterpret_cast<__half2*>(&O16[(size_t)(r0+8)*N + c]) = __floats2half2_rn(v2, v3);
            }
        }
}

// ---------------- weight convert: fp32 -> fp16 (scaled) ----------------
__global__ __launch_bounds__(256)
void conv_kernel(const float* __restrict__ src, __half* __restrict__ dst, int n4, float sc)
{
    int i = blockIdx.x * blockDim.x + threadIdx.x;
    if (i >= n4) return;
    float4 v = reinterpret_cast<const float4*>(src)[i];
    reinterpret_cast<__half2*>(dst)[i*2]   = __floats2half2_rn(v.x * sc, v.y * sc);
    reinterpret_cast<__half2*>(dst)[i*2+1] = __floats2half2_rn(v.z * sc, v.w * sc);
}

// ---------------- LayerNorm (+ modulation), writes single fp16 ----------------
__global__ __launch_bounds__(256)
void ln_kernel(const float* __restrict__ x, const float* __restrict__ latents,
               const float* __restrict__ shift, const float* __restrict__ scale,
               const float* __restrict__ ln1w, const float* __restrict__ ln1b,
               const float* __restrict__ ln2w, const float* __restrict__ ln2b)
{
    const int row = blockIdx.x, batch = row / L_, local = row % L_;
    const bool is_lat = (local >= N1_);
    const float* src = is_lat
        ? latents + ((size_t)batch * N2_ + (local - N1_)) * D_
        : x + ((size_t)batch * N1_ + local) * D_;

    const int t = threadIdx.x;
    float4 v = reinterpret_cast<const float4*>(src)[t];
    float s = v.x + v.y + v.z + v.w;
    float sq = v.x*v.x + v.y*v.y + v.z*v.z + v.w*v.w;

    __shared__ float red[16], red2[16];
    for (int o = 16; o > 0; o >>= 1) {
        s  += __shfl_down_sync(0xffffffff, s, o);
        sq += __shfl_down_sync(0xffffffff, sq, o);
    }
    int warp = t >> 5, lane = t & 31;
    if (lane == 0) { red[warp] = s; red2[warp] = sq; }
    __syncthreads();
    if (warp == 0) {
        s = (lane < 8) ? red[lane] : 0.f;
        sq = (lane < 8) ? red2[lane] : 0.f;
        for (int o = 4; o > 0; o >>= 1) {
            s  += __shfl_down_sync(0xffffffff, s, o);
            sq += __shfl_down_sync(0xffffffff, sq, o);
        }
        if (lane == 0) { red[0] = s; red2[0] = sq; }
    }
    __syncthreads();
    const float mu = red[0] * (1.0f / D_);
    const float var = red2[0] * (1.0f / D_) - mu * mu;
    const float rstd = rsqrtf(var + EPS_);

    float4 w4, b4, out;
    if (is_lat) {
        w4 = reinterpret_cast<const float4*>(ln2w)[t];
        b4 = reinterpret_cast<const float4*>(ln2b)[t];
    } else {
        w4 = reinterpret_cast<const float4*>(ln1w)[t];
        b4 = reinterpret_cast<const float4*>(ln1b)[t];
    }
    out.x = (v.x - mu) * rstd * w4.x + b4.x;
    out.y = (v.y - mu) * rstd * w4.y + b4.y;
    out.z = (v.z - mu) * rstd * w4.z + b4.z;
    out.w = (v.w - mu) * rstd * w4.w + b4.w;

    if (is_lat) {
        const float4 sc = reinterpret_cast<const float4*>(scale + (size_t)batch * D_)[t];
        const float4 sh = reinterpret_cast<const float4*>(shift + (size_t)batch * D_)[t];
        out.x = out.x * (1.0f + sc.x) + sh.x;
        out.y = out.y * (1.0f + sc.y) + sh.y;
        out.z = out.z * (1.0f + sc.z) + sh.z;
        out.w = out.w * (1.0f + sc.w) + sh.w;
    }

    __half2 hA = __floats2half2_rn(out.x, out.y);
    __half2 hB = __floats2half2_rn(out.z, out.w);
    {
        __half2* hp = reinterpret_cast<__half2*>(g_kvin16 + (size_t)row * D_);
        hp[t*2] = hA; hp[t*2+1] = hB;
    }
    if (is_lat) {
        const size_t lr = (size_t)batch * N2_ + (local - N1_);
        __half2* hp = reinterpret_cast<__half2*>(g_latm16 + lr * D_);
        hp[t*2] = hA; hp[t*2+1] = hB;
    }
}

// ============================ mma.sync flash attention (fp16) ============================
#define AT_ROWB 144
#define AK_BASE 18432
#define AK_STAGE 18432
#define AV 9216
#define A_SMEM 55296

__global__ __launch_bounds__(256, 1)
void attn_mma(const __half* __restrict__ q16, const __half* __restrict__ k16,
              const __half* __restrict__ v16, __half* __restrict__ att)
{
    extern __shared__ char sm[];
    const uint32_t smb = smem_u32(sm);
    const int tid = threadIdx.x, wid = tid >> 5, lane = tid & 31;
    const int batch = blockIdx.x >> 4, head = blockIdx.x & 15;
    const int q0 = batch * N2_ + blockIdx.y * 128;
    const size_t kv0 = (size_t)batch * L_;

    for (int i = tid; i < 1024; i += 256) {
        const int row = i >> 3, ch = (i & 7) * 16;
        const size_t g = ((size_t)(q0 + row) * INNER_ + head * DH_) * 2;
        CP_ASYNC16(smb + row * AT_ROWB + ch, (const char*)q16 + g + ch);
    }
    CP_COMMIT();

    auto load_kv = [&](int t, int st) {
        const uint32_t sb = smb + AK_BASE + st * AK_STAGE;
        for (int i = tid; i < 512; i += 256) {
            const int row = i >> 3, ch = (i & 7) * 16;
            const size_t gr = kv0 + t * 64 + row;
            const size_t gk = (gr * INNER_ + head * DH_) * 2;
            CP_ASYNC16(sb + row * AT_ROWB + ch, (const char*)k16 + gk + ch);
            CP_ASYNC16(sb + AV + row * AT_ROWB + ch, (const char*)v16 + gk + ch);
        }
        CP_COMMIT();
    };

    load_kv(0, 0);
    CP_WAIT(0);
    __syncthreads();

    uint32_t qf[4][4];
    #pragma unroll
    for (int kk = 0; kk < 4; kk++) {
        const uint32_t ra = smb + (wid * 16 + (lane & 15)) * AT_ROWB + ((lane >> 4) << 4) + kk * 32;
        LDSM_X4(qf[kk], ra);
    }

    float accO[8][4];
    #pragma unroll
    for (int nt = 0; nt < 8; nt++)
        #pragma unroll
        for (int c = 0; c < 4; c++) accO[nt][c] = 0.f;
    float m0 = -1e30f, m1 = -1e30f, l0 = 0.f, l1 = 0.f;

    const int NT = L_ / 64;
    for (int t = 0; t < NT; t++) {
        const int st = t & 1;
        if (t > 0) { CP_WAIT(0); __syncthreads(); }
        if (t + 1 < NT) load_kv(t + 1, st ^ 1);
        const uint32_t sb = smb + AK_BASE + st * AK_STAGE;

        float sacc[8][4];
        #pragma unroll
        for (int nt = 0; nt < 8; nt++)
            #pragma unroll
            for (int c = 0; c < 4; c++) sacc[nt][c] = 0.f;

        #pragma unroll
        for (int kk = 0; kk < 4; kk++) {
            uint32_t kb[4][4];
            #pragma unroll
            for (int g = 0; g < 4; g++) {
                const uint32_t rb = sb + (g * 16 + ((lane >> 4) << 3) + (lane & 7)) * AT_ROWB
                                    + (((lane >> 3) & 1) << 4) + kk * 32;
                LDSM_X4(kb[g], rb);
            }
            #pragma unroll
            for (int g = 0; g < 4; g++) {
                MMAF16(sacc[2*g],   qf[kk], kb[g][0], kb[g][1]);
                MMAF16(sacc[2*g+1], qf[kk], kb[g][2], kb[g][3]);
            }
        }

        float tm0 = sacc[0][0], tm1 = sacc[0][2];
        #pragma unroll
        for (int nt = 0; nt < 8; nt++) {
            tm0 = fmaxf(tm0, fmaxf(sacc[nt][0], sacc[nt][1]));
            tm1 = fmaxf(tm1, fmaxf(sacc[nt][2], sacc[nt][3]));
        }
        tm0 = fmaxf(tm0, __shfl_xor_sync(0xffffffff, tm0, 1));
        tm0 = fmaxf(tm0, __shfl_xor_sync(0xffffffff, tm0, 2));
        tm1 = fmaxf(tm1, __shfl_xor_sync(0xffffffff, tm1, 1));
        tm1 = fmaxf(tm1, __shfl_xor_sync(0xffffffff, tm1, 2));

        const float mn0 = fmaxf(m0, tm0), mn1 = fmaxf(m1, tm1);
        const float c0 = exp2f(m0 - mn0), c1 = exp2f(m1 - mn1);
        m0 = mn0; m1 = mn1;

        float ls0 = 0.f, ls1 = 0.f;
        uint32_t pa[4][4];
        #pragma unroll
        for (int nt = 0; nt < 8; nt++) {
            const float p0 = exp2f(sacc[nt][0] - mn0);
            const float p1 = exp2f(sacc[nt][1] - mn0);
            const float p2 = exp2f(sacc[nt][2] - mn1);
            const float p3 = exp2f(sacc[nt][3] - mn1);
            ls0 += p0 + p1; ls1 += p2 + p3;
            __half2 ha = __floats2half2_rn(p0, p1);
            __half2 hb = __floats2half2_rn(p2, p3);
            pa[nt >> 1][(nt & 1) * 2 + 0] = *reinterpret_cast<uint32_t*>(&ha);
            pa[nt >> 1][(nt & 1) * 2 + 1] = *reinterpret_cast<uint32_t*>(&hb);
        }
        l0 = l0 * c0 + ls0;
        l1 = l1 * c1 + ls1;
        #pragma unroll
        for (int nt = 0; nt < 8; nt++) {
            accO[nt][0] *= c0; accO[nt][1] *= c0;
            accO[nt][2] *= c1; accO[nt][3] *= c1;
        }

        #pragma unroll
        for (int kt = 0; kt < 4; kt++) {
            uint32_t vb[4][4];
            #pragma unroll
            for (int g = 0; g < 4; g++) {
                const uint32_t rv = sb + AV + (kt * 16 + (lane & 15)) * AT_ROWB
                                    + g * 32 + ((lane >> 4) << 4);
                LDSM_X4_T(vb[g], rv);
            }
            #pragma unroll
            for (int g = 0; g < 4; g++) {
                MMAF16(accO[2*g],   pa[kt], vb[g][0], vb[g][1]);
                MMAF16(accO[2*g+1], pa[kt], vb[g][2], vb[g][3]);
            }
        }
    }

    l0 += __shfl_xor_sync(0xffffffff, l0, 1);
    l0 += __shfl_xor_sync(0xffffffff, l0, 2);
    l1 += __shfl_xor_sync(0xffffffff, l1, 1);
    l1 += __shfl_xor_sync(0xffffffff, l1, 2);
    const float i0 = 1.0f / l0, i1 = 1.0f / l1;

    const int qrow = q0 + wid * 16 + (lane >> 2);
    #pragma unroll
    for (int nt = 0; nt < 8; nt++) {
        const int col = head * DH_ + nt * 8 + (lane & 3) * 2;
        *reinterpret_cast<__half2*>(att + (size_t)qrow*INNER_ + col) =
            __floats2half2_rn(accO[nt][0]*i0, accO[nt][1]*i0);
        *reinterpret_cast<__half2*>(att + (size_t)(qrow+8)*INNER_ + col) =
            __floats2half2_rn(accO[nt][2]*i1, accO[nt][3]*i1);
    }
}

// ---------------- launch ----------------
extern "C" void kernel_launch(void* const* d_in, const int* in_sizes, int n_in,
                              void* d_out, int out_size)
{
    const float* x       = (const float*)d_in[0];
    const float* latents = (const float*)d_in[1];
    const float* shift   = (const float*)d_in[2];
    const float* scale   = (const float*)d_in[3];
    const float* ln1w    = (const float*)d_in[4];
    const float* ln1b    = (const float*)d_in[5];
    const float* ln2w    = (const float*)d_in[6];
    const float* ln2b    = (const float*)d_in[7];
    const float* Wq      = (const float*)d_in[8];
    const float* Wkv     = (const float*)d_in[9];
    const float* Wo      = (const float*)d_in[10];
    float* out = (float*)d_out;

    __half *kvin16,*latm16,*wq16,*wkv16,*wo16,*att16,*q16,*k16,*v16;
    cudaGetSymbolAddress((void**)&kvin16, g_kvin16);
    cudaGetSymbolAddress((void**)&latm16, g_latm16);
    cudaGetSymbolAddress((void**)&wq16, g_wq16);
    cudaGetSymbolAddress((void**)&wkv16, g_wkv16);
    cudaGetSymbolAddress((void**)&wo16, g_wo16);
    cudaGetSymbolAddress((void**)&att16, g_att16);
    cudaGetSymbolAddress((void**)&q16, g_q16);
    cudaGetSymbolAddress((void**)&k16, g_k16);
    cudaGetSymbolAddress((void**)&v16, g_v16);

    cudaFuncSetAttribute(gemm_f16, cudaFuncAttributeMaxDynamicSharedMemorySize, 3 * GS_STAGE);
    cudaFuncSetAttribute(attn_mma, cudaFuncAttributeMaxDynamicSharedMemorySize, A_SMEM);

    const float qsc = 0.125f * 1.44269504088896340736f;  // attn_scale^2 * log2(e)
    conv_kernel<<<INNER_ * D_ / 1024, 256>>>(Wq, wq16, INNER_ * D_ / 4, qsc);
    conv_kernel<<<2 * INNER_ * D_ / 1024, 256>>>(Wkv, wkv16, 2 * INNER_ * D_ / 4, 1.0f);
    conv_kernel<<<D_ * INNER_ / 1024, 256>>>(Wo, wo16, D_ * INNER_ / 4, 1.0f);

    ln_kernel<<<B_ * L_, 256>>>(x, latents, shift, scale, ln1w, ln1b, ln2w, ln2b);

    { // q = latm @ (qsc*Wq)^T, fp16 out
        dim3 grid(INNER_ / 256, (B_ * N2_) / 128);
        gemm_f16<<<grid, 256, 3 * GS_STAGE>>>(latm16, wq16,
                                              nullptr, nullptr, nullptr, q16, INNER_, D_, 3);
    }
    { // fused KV: K16 + V16 out
        dim3 grid((2 * INNER_) / 256, (B_ * L_) / 128);
        gemm_f16<<<grid, 256, 3 * GS_STAGE>>>(kvin16, wkv16,
                                              nullptr, k16, v16, nullptr, 2 * INNER_, D_, 2);
    }
    { // attention
        dim3 grid(B_ * HEADS_, N2_ / 128);
        attn_mma<<<grid, 256, A_SMEM>>>(q16, k16, v16, att16);
    }
    { // out = att @ Wo^T, fp32 out
        dim3 grid(D_ / 256, (B_ * N2_) / 128);
        gemm_f16<<<grid, 256, 3 * GS_STAGE>>>(att16, wo16,
                                              out, nullptr, nullptr, nullptr, D_, INNER_, 0);
    }
    (void)in_sizes; (void)n_in; (void)out_size;
}